// round 11
// baseline (speedup 1.0000x reference)
#include <cuda_runtime.h>
#include <cuda_bf16.h>
#include <math.h>
#include <stdint.h>

#define NB 1024
#define ND 64
#define NH 512

typedef __nv_bfloat16 bf16;

// ---------------- fp32 scratch ----------------
__device__ __align__(256) float g_W1T[NH*ND];   // [k,i] = W1[i,k]
__device__ __align__(256) float g_w3s[NH];
__device__ __align__(256) float g_h1 [NB*NH];
__device__ __align__(256) float g_h2 [NB*NH];
__device__ __align__(256) float g_U  [NB*NH];
__device__ __align__(256) float g_V  [NB*NH];
__device__ __align__(256) float g_r1 [NB*NH];   // qw
__device__ __align__(256) float g_r2 [NB*NH];   // z2
__device__ __align__(256) float g_s  [NB*ND];
__device__ __align__(256) float g_y  [NB*ND];
__device__ __align__(256) float g_st [NB];

// ---------------- bf16 hi/lo pre-split scratch ----------------
__device__ __align__(256) bf16 g_W1Ts_h[NH*ND], g_W1Ts_l[NH*ND]; // [n,k]=W1[k,n]
__device__ __align__(256) bf16 g_W3s_h [NH*ND], g_W3s_l [NH*ND]; // [n,j]=W3[n,j]
__device__ __align__(256) bf16 g_W2Ts_h[NH*NH], g_W2Ts_l[NH*NH]; // [n,k]=W2[k,n]
__device__ __align__(256) bf16 g_W2s_h [NH*NH], g_W2s_l [NH*NH]; // [n,k]=W2[n,k]
__device__ __align__(256) bf16 g_As_h  [NH*NH], g_As_l  [NH*NH]; // [n,k]=A[n,k]
__device__ __align__(256) bf16 g_ATs_h [NH*NH], g_ATs_l [NH*NH]; // [n,k]=A[k,n]
__device__ __align__(256) bf16 g_h1s_h [NB*NH], g_h1s_l [NB*NH];
__device__ __align__(256) bf16 g_d1s_h [NB*NH], g_d1s_l [NB*NH];
__device__ __align__(256) bf16 g_a1s_h [NB*NH], g_a1s_l [NB*NH];
__device__ __align__(256) bf16 g_a2s_h [NB*NH], g_a2s_l [NB*NH];
__device__ __align__(256) bf16 g_wbs_h [NB*NH], g_wbs_l [NB*NH];

// ---------------- helpers ------------------------------------------------
__device__ __forceinline__ uint32_t smem_u32(const void* p) {
    return (uint32_t)__cvta_generic_to_shared(p);
}
__device__ __forceinline__ void sts_v2(uint32_t addr, uint32_t a, uint32_t b) {
    asm volatile("st.shared.v2.b32 [%0], {%1,%2};" :: "r"(addr), "r"(a), "r"(b));
}
__device__ __forceinline__ void cp16(uint32_t saddr, const void* gaddr) {
    asm volatile("cp.async.cg.shared.global [%0], [%1], 16;"
                 :: "r"(saddr), "l"(gaddr));
}
__device__ __forceinline__ void cp_commit() {
    asm volatile("cp.async.commit_group;" ::: "memory");
}
template<int N> __device__ __forceinline__ void cp_wait() {
    asm volatile("cp.async.wait_group %0;" :: "n"(N) : "memory");
}
__device__ __forceinline__ void split2(float x0, float x1, uint32_t& hi, uint32_t& lo) {
    bf16 h0 = __float2bfloat16(x0), h1 = __float2bfloat16(x1);
    bf16 l0 = __float2bfloat16(x0 - __bfloat162float(h0));
    bf16 l1 = __float2bfloat16(x1 - __bfloat162float(h1));
    __nv_bfloat162 H; H.x = h0; H.y = h1;
    __nv_bfloat162 L; L.x = l0; L.y = l1;
    hi = *reinterpret_cast<uint32_t*>(&H);
    lo = *reinterpret_cast<uint32_t*>(&L);
}
__device__ __forceinline__ void splitf(float v, bf16* H, bf16* L, size_t idx) {
    bf16 h = __float2bfloat16(v);
    H[idx] = h;
    L[idx] = __float2bfloat16(v - __bfloat162float(h));
}
__device__ __forceinline__ void store_split(bf16* H, bf16* L, size_t idx,
                                            float v0, float v1) {
    uint32_t hi, lo; split2(v0, v1, hi, lo);
    *reinterpret_cast<uint32_t*>(H + idx) = hi;
    *reinterpret_cast<uint32_t*>(L + idx) = lo;
}
__device__ __forceinline__ void ldsm_x4(uint32_t* r, uint32_t addr) {
    asm volatile("ldmatrix.sync.aligned.m8n8.x4.shared.b16 {%0,%1,%2,%3}, [%4];"
                 : "=r"(r[0]), "=r"(r[1]), "=r"(r[2]), "=r"(r[3]) : "r"(addr));
}
__device__ __forceinline__ void ldsm_x2(uint32_t* r, uint32_t addr) {
    asm volatile("ldmatrix.sync.aligned.m8n8.x2.shared.b16 {%0,%1}, [%2];"
                 : "=r"(r[0]), "=r"(r[1]) : "r"(addr));
}
__device__ __forceinline__ void mma16816(float* c, const uint32_t* a, const uint32_t* b) {
    asm volatile(
        "mma.sync.aligned.m16n8k16.row.col.f32.bf16.bf16.f32 "
        "{%0,%1,%2,%3}, {%4,%5,%6,%7}, {%8,%9}, {%0,%1,%2,%3};"
        : "+f"(c[0]), "+f"(c[1]), "+f"(c[2]), "+f"(c[3])
        : "r"(a[0]), "r"(a[1]), "r"(a[2]), "r"(a[3]), "r"(b[0]), "r"(b[1]));
}
__device__ __forceinline__ uint32_t sw128(uint32_t byte) {
    return byte ^ ((byte >> 3) & 0x70);
}

// ---------------- prep: weights + derived matrices, pre-split ----------------
__global__ void prep_kernel(const float* __restrict__ W1,
                            const float* __restrict__ W2,
                            const float* __restrict__ W3) {
    __shared__ float w2ts[16][17];
    const int tx = threadIdx.x, ty = threadIdx.y;
    const int r = blockIdx.y * 16 + ty;
    const int c = blockIdx.x * 16 + tx;
    w2ts[ty][tx] = W2[(size_t)(blockIdx.x * 16 + ty) * NH + blockIdx.y * 16 + tx];
    __syncthreads();
    float w2rc = W2[(size_t)r * NH + c];
    float w2cr = w2ts[tx][ty];
    float d1 = 0.f, d2 = 0.f;
#pragma unroll
    for (int i = 0; i < ND; i++) {
        d1 += W3[c * ND + i] * W1[i * NH + r];
        d2 += W3[r * ND + i] * W1[i * NH + c];
    }
    const size_t idx = (size_t)r * NH + c;
    splitf(w2rc,      g_W2s_h,  g_W2s_l,  idx);
    splitf(w2cr,      g_W2Ts_h, g_W2Ts_l, idx);
    splitf(w2rc * d1, g_As_h,   g_As_l,   idx);   // A[r,c]
    splitf(w2cr * d2, g_ATs_h,  g_ATs_l,  idx);   // A[c,r]
    if (c < ND) {
        float w1v = W1[c * NH + r];
        g_W1T[r * ND + c] = w1v;
        splitf(w1v,          g_W1Ts_h, g_W1Ts_l, (size_t)r * ND + c);
        splitf(W3[r*ND + c], g_W3s_h,  g_W3s_l,  (size_t)r * ND + c);
    }
    if (blockIdx.y == 0 && ty == 0) {
        float s1 = 0.f;
#pragma unroll
        for (int j = 0; j < ND; j++) s1 += W3[c * ND + j];
        g_w3s[c] = s1;
    }
}

// ---------------- tensor GEMMs -----------------------------------------------
// PIPE kernels use BN=32 tiles + small blocks for 2-4 CTAs/SM occupancy.
enum { TM_L1 = 0, TM_H2 = 1, TM_VU = 2, TM_P = 3, TM_QW = 4 };

template<int TMODE, int BM, int BN, int NTHR>
__global__ void __launch_bounds__(NTHR, 1)
tmma(const float* __restrict__ pX, const float* __restrict__ pC,
     const float* __restrict__ pT, const float* __restrict__ w1row) {
    extern __shared__ __align__(1024) char tsm[];
    const uint32_t sb = smem_u32(tsm);
    constexpr bool PIPE = (TMODE == TM_H2 || TMODE == TM_VU || TMODE == TM_QW);
    constexpr int NCHUNK = PIPE ? 8 : 1;
    constexpr int NSTAGE = PIPE ? 2 : 1;
    constexpr uint32_t XSZ = BM * 128;
    constexpr uint32_t BSZ = BN * 128;
    constexpr uint32_t OXH = 0, OXL = XSZ, OBH = 2 * XSZ, OBL = 2 * XSZ + BSZ;
    constexpr uint32_t STAGE = 2 * XSZ + 2 * BSZ;
    constexpr int NT = 2;                                 // n microtiles per warp
    constexpr int LDBW = (TMODE == TM_L1 || TMODE == TM_P) ? ND : NH;
    constexpr int MSLOTS = BM / 32;                       // warp m-slots

    const int tid = threadIdx.x, lane = tid & 31, wid = tid >> 5;
    const int zm = blockIdx.z;
    const int n0 = blockIdx.x * BN, m0 = blockIdx.y * BM;
    const int wm = (wid & (MSLOTS - 1)) * 32;
    const int wn = (wid / MSLOTS) * 16;

    const bf16 *Xh = nullptr, *Xl = nullptr;
    if constexpr (TMODE == TM_H2) {
        Xh = (zm == 0) ? g_h1s_h : (zm == 1) ? g_d1s_h : g_a1s_h;
        Xl = (zm == 0) ? g_h1s_l : (zm == 1) ? g_d1s_l : g_a1s_l;
    }
    else if constexpr (TMODE == TM_VU) { Xh = g_a2s_h; Xl = g_a2s_l; }
    else if constexpr (TMODE == TM_QW) { Xh = g_wbs_h; Xl = g_wbs_l; }
    const bf16 *Bh, *Bl;
    if constexpr (TMODE == TM_L1)      { Bh = g_W1Ts_h; Bl = g_W1Ts_l; }
    else if constexpr (TMODE == TM_H2) {
        Bh = (zm <= 1) ? g_W2Ts_h : g_ATs_h;
        Bl = (zm <= 1) ? g_W2Ts_l : g_ATs_l;
    }
    else if constexpr (TMODE == TM_VU) { Bh = g_As_h; Bl = g_As_l; }
    else if constexpr (TMODE == TM_P)  { Bh = g_W3s_h; Bl = g_W3s_l; }
    else                               { Bh = g_W2s_h; Bl = g_W2s_l; }

    // X loader mapping (PIPE): NTHR == 2*BM, 4 cp16 per array per thread
    const int xrow = tid >> 1;
    const int xcb  = (tid & 1) * 32;
    // B loader mapping: TPB threads per row
    constexpr int TPB = NTHR / BN;
    constexpr int NIB = 8 / TPB;          // 16B groups per thread per row
    const int brow = tid / TPB;
    const int bcb  = (tid % TPB) * (64 / TPB);

    auto cpX = [&](int ch, uint32_t st) {
        size_t base = (size_t)(m0 + xrow) * NH + ch * 64 + xcb;
#pragma unroll
        for (int i = 0; i < 4; i++) {
            int col = xcb + i * 8;
            uint32_t sw = sw128((uint32_t)xrow * 128 + col * 2);
            cp16(st + OXH + sw, Xh + base + i * 8);
            cp16(st + OXL + sw, Xl + base + i * 8);
        }
    };
    auto cpB = [&](int ch, uint32_t st) {
        size_t base = (size_t)(n0 + brow) * LDBW + (PIPE ? ch * 64 : 0) + bcb;
#pragma unroll
        for (int i = 0; i < NIB; i++) {
            int col = bcb + i * 8;
            uint32_t sw = sw128((uint32_t)brow * 128 + col * 2);
            cp16(st + OBH + sw, Bh + base + i * 8);
            cp16(st + OBL + sw, Bl + base + i * 8);
        }
    };
    auto stXinline = [&](uint32_t st) {   // L1 / P only (BM=64, NTHR=256, fp32)
        const int row = tid >> 2, cb = (tid & 3) * 16;
        const float* src = (TMODE == TM_L1) ? pX : g_y;
        const float* xr = src + (size_t)(m0 + row) * 64 + cb;
#pragma unroll
        for (int i = 0; i < 4; i++) {
            float4 v = *(const float4*)(xr + i * 4);
            uint32_t h01, l01, h23, l23;
            split2(v.x, v.y, h01, l01);
            split2(v.z, v.w, h23, l23);
            uint32_t sw = sw128((uint32_t)row * 128 + (cb + i * 4) * 2);
            sts_v2(st + OXH + sw, h01, h23);
            sts_v2(st + OXL + sw, l01, l23);
        }
    };

    float acc[2][NT][4];
#pragma unroll
    for (int mt = 0; mt < 2; mt++)
#pragma unroll
        for (int nt = 0; nt < NT; nt++)
#pragma unroll
            for (int i = 0; i < 4; i++) acc[mt][nt][i] = 0.f;

    if constexpr (PIPE) {
        cpX(0, sb); cpB(0, sb); cp_commit();
    } else {
        cpB(0, sb); cp_commit(); stXinline(sb);
    }

    for (int ch = 0; ch < NCHUNK; ch++) {
        const uint32_t st = sb + (uint32_t)(ch % NSTAGE) * STAGE;
        if constexpr (PIPE) {
            const int pf = ch + NSTAGE - 1;
            if (pf < NCHUNK) {
                const uint32_t st2 = sb + (uint32_t)(pf % NSTAGE) * STAGE;
                cpX(pf, st2); cpB(pf, st2);
            }
            cp_commit();
            cp_wait<NSTAGE - 1>();
        } else {
            cp_wait<0>();
        }
        __syncthreads();

#pragma unroll
        for (int ks = 0; ks < 4; ks++) {
            uint32_t aH[2][4], aL[2][4];
#pragma unroll
            for (int mt = 0; mt < 2; mt++) {
                uint32_t byte = (uint32_t)(wm + mt * 16 + (lane & 15)) * 128
                              + ks * 32 + (lane >> 4) * 16;
                uint32_t sw = sw128(byte);
                ldsm_x4(aH[mt], st + OXH + sw);
                ldsm_x4(aL[mt], st + OXL + sw);
            }
            uint32_t bH[NT][2], bL[NT][2];
#pragma unroll
            for (int nt = 0; nt < NT; nt++) {
                uint32_t byte = (uint32_t)(wn + nt * 8 + (lane & 7)) * 128
                              + ks * 32 + ((lane >> 3) & 1) * 16;
                uint32_t sw = sw128(byte);
                ldsm_x2(bH[nt], st + OBH + sw);
                ldsm_x2(bL[nt], st + OBL + sw);
            }
#pragma unroll
            for (int mt = 0; mt < 2; mt++)
#pragma unroll
                for (int nt = 0; nt < NT; nt++) {
                    mma16816(acc[mt][nt], aH[mt], bH[nt]);
                    mma16816(acc[mt][nt], aH[mt], bL[nt]);
                    mma16816(acc[mt][nt], aL[mt], bH[nt]);
                }
        }
        __syncthreads();
    }

    // ---- epilogues ----
#pragma unroll
    for (int mt = 0; mt < 2; mt++)
#pragma unroll
        for (int nt = 0; nt < NT; nt++) {
            const int r0  = m0 + wm + mt * 16 + (lane >> 2);
            const int col = n0 + wn + nt * 8 + (lane & 3) * 2;
            const float* a = acc[mt][nt];
#pragma unroll
            for (int half = 0; half < 2; half++) {
                const int row = r0 + half * 8;
                const float e0 = a[half * 2], e1 = a[half * 2 + 1];
                const size_t idx = (size_t)row * NH + col;
                if constexpr (TMODE == TM_L1) {
                    float tv = pT[row];
                    float h0 = tanhf(e0 + tv * w1row[col]     + pC[col]);
                    float h1 = tanhf(e1 + tv * w1row[col + 1] + pC[col + 1]);
                    *(float2*)(g_h1 + idx) = make_float2(h0, h1);
                    store_split(g_h1s_h, g_h1s_l, idx, h0, h1);
                    float a0 = 1.f - h0 * h0, a1v = 1.f - h1 * h1;
                    store_split(g_a1s_h, g_a1s_l, idx, a0, a1v);
                    store_split(g_d1s_h, g_d1s_l, idx,
                                a0 * w1row[col], a1v * w1row[col + 1]);
                } else if constexpr (TMODE == TM_H2) {
                    if (zm == 0) {
                        float h0 = tanhf(e0 + pC[col]);
                        float h1 = tanhf(e1 + pC[col + 1]);
                        *(float2*)(g_h2 + idx) = make_float2(h0, h1);
                        store_split(g_a2s_h, g_a2s_l, idx,
                                    1.f - h0 * h0, 1.f - h1 * h1);
                    } else if (zm == 1) {
                        *(float2*)(g_r2 + idx) = make_float2(e0, e1);
                    } else {
                        *(float2*)(g_V + idx) = make_float2(e0, e1);
                    }
                } else if constexpr (TMODE == TM_VU) {
                    *(float2*)(g_U + idx) = make_float2(e0, e1);
                } else if constexpr (TMODE == TM_P) {
                    float2 h = *(const float2*)(g_h2 + idx);
                    float2 v = *(const float2*)(g_V + idx);
                    float w0 = (1.f - h.x * h.x) * (e0 - 2.f * h.x * v.x);
                    float w1 = (1.f - h.y * h.y) * (e1 - 2.f * h.y * v.y);
                    store_split(g_wbs_h, g_wbs_l, idx, w0, w1);
                } else {  // TM_QW
                    *(float2*)(g_r1 + idx) = make_float2(e0, e1);
                }
            }
        }
}

// ---------------- thin SIMT GEMMs (N=64 outputs) ------------------------------
enum { M_S = 2, M_LOSS = 6 };

template<int MODE, int KDIM, int LDA, int LDB>
__global__ void __launch_bounds__(256)
gemm_k(const float* __restrict__ pB, const float* __restrict__ pC,
       const float* __restrict__ pD, float* __restrict__ pOut) {
    constexpr int BK = 32;
    __shared__ __align__(16) float Xs[BK][17];
    __shared__ __align__(16) float Bs[BK][68];
    const int tid = threadIdx.x;
    const int tx = tid & 15, ty = tid >> 4;
    const int m0 = blockIdx.y * 16;
    const float* Bg = (MODE == M_S) ? pB : g_W1T;

    float acc[4] = {0.f, 0.f, 0.f, 0.f};
    float stp = 0.f;
    const int lrow = tid >> 4;
    const int lkc  = (tid & 15) * 2;

    for (int k0 = 0; k0 < KDIM; k0 += BK) {
        {
            size_t idx = (size_t)(m0 + lrow) * LDA + k0 + lkc;
            if constexpr (MODE == M_S) {
                float2 v = *(const float2*)(g_h2 + idx);
                float2 z = *(const float2*)(g_r2 + idx);
                float2 w = *(const float2*)(g_w3s + k0 + lkc);
                stp += (1.f - v.x * v.x) * z.x * w.x
                     + (1.f - v.y * v.y) * z.y * w.y;
                Xs[lkc][lrow] = v.x; Xs[lkc + 1][lrow] = v.y;
            } else {
                float2 q = *(const float2*)(g_r1 + idx);
                float2 h = *(const float2*)(g_h1 + idx);
                float2 u = *(const float2*)(g_U + idx);
                float a0 = 1.f - h.x * h.x, a1v = 1.f - h.y * h.y;
                Xs[lkc][lrow]     = a0  * q.x - 2.f * h.x * a0  * u.x;
                Xs[lkc + 1][lrow] = a1v * q.y - 2.f * h.y * a1v * u.y;
            }
        }
        {
            int brow = tid >> 4, bnq = (tid & 15) * 4;
            *(float4*)&Bs[brow][bnq] =
                *(const float4*)(Bg + (size_t)(k0 + brow) * LDB + bnq);
            *(float4*)&Bs[brow + 16][bnq] =
                *(const float4*)(Bg + (size_t)(k0 + brow + 16) * LDB + bnq);
        }
        __syncthreads();
#pragma unroll
        for (int kk = 0; kk < BK; kk++) {
            float a = Xs[kk][ty];
            float4 b = *(const float4*)&Bs[kk][tx * 4];
            acc[0] += a * b.x; acc[1] += a * b.y;
            acc[2] += a * b.z; acc[3] += a * b.w;
        }
        __syncthreads();
    }
    const int row = m0 + ty, col = tx * 4;
    if constexpr (MODE == M_S) {
#pragma unroll
        for (int o = 8; o; o >>= 1)
            stp += __shfl_xor_sync(0xffffffffu, stp, o, 16);
        if ((tid & 15) == 0) g_st[m0 + lrow] = stp;
#pragma unroll
        for (int c = 0; c < 4; c++) {
            size_t idx = (size_t)row * ND + col + c;
            float sv = acc[c] + pC[col + c];
            g_s[idx] = sv;
            g_y[idx] = 2.f * sv + pD[idx];
        }
    } else {
        float stv = g_st[row], bet = pC[row];
        float ps = 0.f;
#pragma unroll
        for (int c = 0; c < 4; c++) {
            float g = acc[c] + g_s[(size_t)row * ND + col + c];
            ps += fabsf(stv - 0.5f * bet * g);
        }
#pragma unroll
        for (int o = 8; o; o >>= 1) ps += __shfl_xor_sync(0xffffffffu, ps, o);
        if (tx == 0) pOut[row] = ps * (1.f / 64.f);
    }
}

// ---------------- launch -----------------------------------------------------
// smem: stage = 2*BM*128 + 2*BN*128
#define SM_H2   (2 * (2 * 128 * 128 + 2 * 32 * 128))   // 81920 (2-stage, 128x32)
#define SM_U    (2 * (2 * 64 * 128 + 2 * 32 * 128))    // 49152 (2-stage, 64x32)
#define SM_S64  (2 * 64 * 128 + 2 * 64 * 128)          // 32768 (single, 64x64)

extern "C" void kernel_launch(void* const* d_in, const int* in_sizes, int n_in,
                              void* d_out, int out_size) {
    const float* x    = (const float*)d_in[0];
    const float* t    = (const float*)d_in[1];
    const float* beta = (const float*)d_in[2];
    const float* W1   = (const float*)d_in[3];
    const float* b1   = (const float*)d_in[4];
    const float* W2   = (const float*)d_in[5];
    const float* b2   = (const float*)d_in[6];
    const float* W3   = (const float*)d_in[7];
    const float* b3   = (const float*)d_in[8];
    float* out = (float*)d_out;
    const float* w1t = W1 + (size_t)ND * NH;   // W1 t-row

    cudaFuncSetAttribute((const void*)tmma<TM_L1, 64, 64, 256>,
                         cudaFuncAttributeMaxDynamicSharedMemorySize, SM_S64);
    cudaFuncSetAttribute((const void*)tmma<TM_H2, 128, 32, 256>,
                         cudaFuncAttributeMaxDynamicSharedMemorySize, SM_H2);
    cudaFuncSetAttribute((const void*)tmma<TM_VU, 64, 32, 128>,
                         cudaFuncAttributeMaxDynamicSharedMemorySize, SM_U);
    cudaFuncSetAttribute((const void*)tmma<TM_P, 64, 64, 256>,
                         cudaFuncAttributeMaxDynamicSharedMemorySize, SM_S64);
    cudaFuncSetAttribute((const void*)tmma<TM_QW, 64, 32, 128>,
                         cudaFuncAttributeMaxDynamicSharedMemorySize, SM_U);

    dim3 gThin(1, NB/16);             // 64 blocks
    dim3 gH2  (NH/32, NB/128, 3);     // (16,8,3) = 384 blocks, 2 CTA/SM
    dim3 gU   (NH/32, NB/64);         // (16,16)  = 256 blocks, 4 CTA/SM
    dim3 gT64 (NH/64, NB/64);         // (8,16)   = 128 blocks

    prep_kernel<<<dim3(NH/16, NH/16), dim3(16,16)>>>(W1, W2, W3);
    // h1 = tanh([x,t]@W1 + b1); writes h1, h1s, a1s, d1s
    tmma<TM_L1, 64, 64, 256><<<gT64, 256, SM_S64>>>(x, b1, t, w1t);
    // z0: h2 = tanh(h1@W2 + b2) (+a2s); z1: z2 = d1@W2; z2: V = a1@A
    tmma<TM_H2, 128, 32, 256><<<gH2, 256, SM_H2>>>(nullptr, b2, nullptr, nullptr);
    // U = a2@A^T   (4th launch -> ncu capture target)
    tmma<TM_VU, 64, 32, 128><<<gU, 128, SM_U>>>(nullptr, nullptr, nullptr, nullptr);
    // s = h2@W3 + b3; y = 2s + x; s_t fused
    gemm_k<M_S, NH, NH, ND><<<gThin, 256>>>(W3, b3, x, nullptr);
    // P = y@W3^T; wb = a2*(P - 2 h2 V) -> wbs
    tmma<TM_P, 64, 64, 256><<<gT64, 256, SM_S64>>>(nullptr, nullptr, nullptr, nullptr);
    // qw = wb@W2^T
    tmma<TM_QW, 64, 32, 128><<<gU, 128, SM_U>>>(nullptr, nullptr, nullptr, nullptr);
    // c on the fly; G = c@W1x^T + s; loss
    gemm_k<M_LOSS, NH, NH, ND><<<gThin, 256>>>(nullptr, beta, nullptr, out);
}

// round 12
// speedup vs baseline: 1.0033x; 1.0033x over previous
#include <cuda_runtime.h>
#include <cuda_bf16.h>
#include <math.h>
#include <stdint.h>

#define NB 1024
#define ND 64
#define NH 512

typedef __nv_bfloat16 bf16;

// ---------------- fp32 scratch ----------------
__device__ __align__(256) float g_W1T[NH*ND];   // [k,i] = W1[i,k]
__device__ __align__(256) float g_w3s[NH];
__device__ __align__(256) float g_h1 [NB*NH];
__device__ __align__(256) float g_h2 [NB*NH];
__device__ __align__(256) float g_U  [NB*NH];
__device__ __align__(256) float g_V  [NB*NH];
__device__ __align__(256) float g_r1 [NB*NH];   // qw
__device__ __align__(256) float g_r2 [NB*NH];   // z2
__device__ __align__(256) float g_s  [NB*ND];
__device__ __align__(256) float g_y  [NB*ND];
__device__ __align__(256) float g_st [NB];

// ---------------- bf16 hi/lo pre-split scratch ----------------
__device__ __align__(256) bf16 g_W1Ts_h[NH*ND], g_W1Ts_l[NH*ND]; // [n,k]=W1[k,n]
__device__ __align__(256) bf16 g_W3s_h [NH*ND], g_W3s_l [NH*ND]; // [n,j]=W3[n,j]
__device__ __align__(256) bf16 g_W2Ts_h[NH*NH], g_W2Ts_l[NH*NH]; // [n,k]=W2[k,n]
__device__ __align__(256) bf16 g_W2s_h [NH*NH], g_W2s_l [NH*NH]; // [n,k]=W2[n,k]
__device__ __align__(256) bf16 g_As_h  [NH*NH], g_As_l  [NH*NH]; // [n,k]=A[n,k]
__device__ __align__(256) bf16 g_ATs_h [NH*NH], g_ATs_l [NH*NH]; // [n,k]=A[k,n]
__device__ __align__(256) bf16 g_h1s_h [NB*NH], g_h1s_l [NB*NH];
__device__ __align__(256) bf16 g_d1s_h [NB*NH], g_d1s_l [NB*NH];
__device__ __align__(256) bf16 g_a1s_h [NB*NH], g_a1s_l [NB*NH];
__device__ __align__(256) bf16 g_a2s_h [NB*NH], g_a2s_l [NB*NH];
__device__ __align__(256) bf16 g_wbs_h [NB*NH], g_wbs_l [NB*NH];

// ---------------- helpers ------------------------------------------------
__device__ __forceinline__ uint32_t smem_u32(const void* p) {
    return (uint32_t)__cvta_generic_to_shared(p);
}
__device__ __forceinline__ void sts_v2(uint32_t addr, uint32_t a, uint32_t b) {
    asm volatile("st.shared.v2.b32 [%0], {%1,%2};" :: "r"(addr), "r"(a), "r"(b));
}
__device__ __forceinline__ void cp16(uint32_t saddr, const void* gaddr) {
    asm volatile("cp.async.cg.shared.global [%0], [%1], 16;"
                 :: "r"(saddr), "l"(gaddr));
}
__device__ __forceinline__ void cp_commit() {
    asm volatile("cp.async.commit_group;" ::: "memory");
}
template<int N> __device__ __forceinline__ void cp_wait() {
    asm volatile("cp.async.wait_group %0;" :: "n"(N) : "memory");
}
__device__ __forceinline__ void split2(float x0, float x1, uint32_t& hi, uint32_t& lo) {
    bf16 h0 = __float2bfloat16(x0), h1 = __float2bfloat16(x1);
    bf16 l0 = __float2bfloat16(x0 - __bfloat162float(h0));
    bf16 l1 = __float2bfloat16(x1 - __bfloat162float(h1));
    __nv_bfloat162 H; H.x = h0; H.y = h1;
    __nv_bfloat162 L; L.x = l0; L.y = l1;
    hi = *reinterpret_cast<uint32_t*>(&H);
    lo = *reinterpret_cast<uint32_t*>(&L);
}
__device__ __forceinline__ void splitf(float v, bf16* H, bf16* L, size_t idx) {
    bf16 h = __float2bfloat16(v);
    H[idx] = h;
    L[idx] = __float2bfloat16(v - __bfloat162float(h));
}
__device__ __forceinline__ void store_split(bf16* H, bf16* L, size_t idx,
                                            float v0, float v1) {
    uint32_t hi, lo; split2(v0, v1, hi, lo);
    *reinterpret_cast<uint32_t*>(H + idx) = hi;
    *reinterpret_cast<uint32_t*>(L + idx) = lo;
}
__device__ __forceinline__ void ldsm_x4(uint32_t* r, uint32_t addr) {
    asm volatile("ldmatrix.sync.aligned.m8n8.x4.shared.b16 {%0,%1,%2,%3}, [%4];"
                 : "=r"(r[0]), "=r"(r[1]), "=r"(r[2]), "=r"(r[3]) : "r"(addr));
}
__device__ __forceinline__ void ldsm_x2(uint32_t* r, uint32_t addr) {
    asm volatile("ldmatrix.sync.aligned.m8n8.x2.shared.b16 {%0,%1}, [%2];"
                 : "=r"(r[0]), "=r"(r[1]) : "r"(addr));
}
__device__ __forceinline__ void mma16816(float* c, const uint32_t* a, const uint32_t* b) {
    asm volatile(
        "mma.sync.aligned.m16n8k16.row.col.f32.bf16.bf16.f32 "
        "{%0,%1,%2,%3}, {%4,%5,%6,%7}, {%8,%9}, {%0,%1,%2,%3};"
        : "+f"(c[0]), "+f"(c[1]), "+f"(c[2]), "+f"(c[3])
        : "r"(a[0]), "r"(a[1]), "r"(a[2]), "r"(a[3]), "r"(b[0]), "r"(b[1]));
}
__device__ __forceinline__ uint32_t sw128(uint32_t byte) {
    return byte ^ ((byte >> 3) & 0x70);
}

// ---------------- prep: weights + derived matrices, pre-split ----------------
__global__ void prep_kernel(const float* __restrict__ W1,
                            const float* __restrict__ W2,
                            const float* __restrict__ W3) {
    __shared__ float w2ts[16][17];
    const int tx = threadIdx.x, ty = threadIdx.y;
    const int r = blockIdx.y * 16 + ty;
    const int c = blockIdx.x * 16 + tx;
    w2ts[ty][tx] = W2[(size_t)(blockIdx.x * 16 + ty) * NH + blockIdx.y * 16 + tx];
    __syncthreads();
    float w2rc = W2[(size_t)r * NH + c];
    float w2cr = w2ts[tx][ty];
    float d1 = 0.f, d2 = 0.f;
#pragma unroll
    for (int i = 0; i < ND; i++) {
        d1 += W3[c * ND + i] * W1[i * NH + r];
        d2 += W3[r * ND + i] * W1[i * NH + c];
    }
    const size_t idx = (size_t)r * NH + c;
    splitf(w2rc,      g_W2s_h,  g_W2s_l,  idx);
    splitf(w2cr,      g_W2Ts_h, g_W2Ts_l, idx);
    splitf(w2rc * d1, g_As_h,   g_As_l,   idx);   // A[r,c]
    splitf(w2cr * d2, g_ATs_h,  g_ATs_l,  idx);   // A[c,r]
    if (c < ND) {
        float w1v = W1[c * NH + r];
        g_W1T[r * ND + c] = w1v;
        splitf(w1v,          g_W1Ts_h, g_W1Ts_l, (size_t)r * ND + c);
        splitf(W3[r*ND + c], g_W3s_h,  g_W3s_l,  (size_t)r * ND + c);
    }
    if (blockIdx.y == 0 && ty == 0) {
        float s1 = 0.f;
#pragma unroll
        for (int j = 0; j < ND; j++) s1 += W3[c * ND + j];
        g_w3s[c] = s1;
    }
}

// ---------------- tensor GEMMs -----------------------------------------------
// TM_H2: 3 z-slices {h2raw, z2, V}; TM_QWU: 2 z-slices {U, qw}.
// Split-bf16 with INDEPENDENT accumulators per MMA term (3x ILP).
enum { TM_L1 = 0, TM_H2 = 1, TM_QWU = 2, TM_P = 3 };

template<int TMODE, int BM>
__global__ void __launch_bounds__(256, 1)
tmma(const float* __restrict__ pX, const float* __restrict__ pC,
     const float* __restrict__ pT, const float* __restrict__ w1row) {
    extern __shared__ __align__(1024) char tsm[];
    const uint32_t sb = smem_u32(tsm);
    constexpr bool PIPE = (TMODE == TM_H2 || TMODE == TM_QWU);
    constexpr int NCHUNK = PIPE ? 8 : 1;
    constexpr int NSTAGE = PIPE ? ((BM == 128) ? 3 : 4) : 1;
    constexpr uint32_t XSZ = BM * 128;
    constexpr uint32_t OXH = 0, OXL = XSZ, OBH = 2 * XSZ, OBL = 2 * XSZ + 8192;
    constexpr uint32_t STAGE = 2 * XSZ + 16384;
    constexpr int NT = (BM == 128) ? 4 : 2;
    constexpr int LDBW = (TMODE == TM_L1 || TMODE == TM_P) ? ND : NH;

    const int tid = threadIdx.x, lane = tid & 31, wid = tid >> 5;
    const int zm = blockIdx.z;
    const int n0 = blockIdx.x * 64, m0 = blockIdx.y * BM;
    const int wm = (BM == 128 ? (wid & 3) : (wid & 1)) * 32;
    const int wn = (BM == 128 ? (wid >> 2) * 32 : (wid >> 1) * 16);

    const bf16 *Xh = nullptr, *Xl = nullptr;
    if constexpr (TMODE == TM_H2) {
        Xh = (zm == 0) ? g_h1s_h : (zm == 1) ? g_d1s_h : g_a1s_h;
        Xl = (zm == 0) ? g_h1s_l : (zm == 1) ? g_d1s_l : g_a1s_l;
    }
    else if constexpr (TMODE == TM_QWU) {
        Xh = zm ? g_wbs_h : g_a2s_h;
        Xl = zm ? g_wbs_l : g_a2s_l;
    }
    const bf16 *Bh, *Bl;
    if constexpr (TMODE == TM_L1)      { Bh = g_W1Ts_h; Bl = g_W1Ts_l; }
    else if constexpr (TMODE == TM_H2) {
        Bh = (zm <= 1) ? g_W2Ts_h : g_ATs_h;
        Bl = (zm <= 1) ? g_W2Ts_l : g_ATs_l;
    }
    else if constexpr (TMODE == TM_QWU) {
        Bh = zm ? g_W2s_h : g_As_h;
        Bl = zm ? g_W2s_l : g_As_l;
    }
    else { Bh = g_W3s_h; Bl = g_W3s_l; }

    const int xrow = (BM == 128) ? (tid >> 1) : (tid >> 2);
    const int xcb  = (BM == 128) ? ((tid & 1) * 32) : ((tid & 3) * 16);
    const int brow = tid >> 2, bcb = (tid & 3) * 16;

    auto cpX = [&](int ch, uint32_t st) {
        constexpr int NI = (BM == 128) ? 4 : 2;
        size_t base = (size_t)(m0 + xrow) * NH + ch * 64 + xcb;
#pragma unroll
        for (int i = 0; i < NI; i++) {
            int col = xcb + i * 8;
            uint32_t sw = sw128((uint32_t)xrow * 128 + col * 2);
            cp16(st + OXH + sw, Xh + base + i * 8);
            cp16(st + OXL + sw, Xl + base + i * 8);
        }
    };
    auto cpB = [&](int ch, uint32_t st) {
        size_t base = (size_t)(n0 + brow) * LDBW + (PIPE ? ch * 64 : 0) + bcb;
#pragma unroll
        for (int i = 0; i < 2; i++) {
            int col = bcb + i * 8;
            uint32_t sw = sw128((uint32_t)brow * 128 + col * 2);
            cp16(st + OBH + sw, Bh + base + i * 8);
            cp16(st + OBL + sw, Bl + base + i * 8);
        }
    };
    auto stXinline = [&](uint32_t st) {   // L1 / P only (BM=64, K=64 fp32)
        const int row = tid >> 2, cb = (tid & 3) * 16;
        const float* src = (TMODE == TM_L1) ? pX : g_y;
        const float* xr = src + (size_t)(m0 + row) * 64 + cb;
#pragma unroll
        for (int i = 0; i < 4; i++) {
            float4 v = *(const float4*)(xr + i * 4);
            uint32_t h01, l01, h23, l23;
            split2(v.x, v.y, h01, l01);
            split2(v.z, v.w, h23, l23);
            uint32_t sw = sw128((uint32_t)row * 128 + (cb + i * 4) * 2);
            sts_v2(st + OXH + sw, h01, h23);
            sts_v2(st + OXL + sw, l01, l23);
        }
    };

    // three independent accumulator banks (one per split term)
    float acc0[2][NT][4], acc1[2][NT][4], acc2[2][NT][4];
#pragma unroll
    for (int mt = 0; mt < 2; mt++)
#pragma unroll
        for (int nt = 0; nt < NT; nt++)
#pragma unroll
            for (int i = 0; i < 4; i++) {
                acc0[mt][nt][i] = 0.f;
                acc1[mt][nt][i] = 0.f;
                acc2[mt][nt][i] = 0.f;
            }

    if constexpr (PIPE) {
#pragma unroll
        for (int s = 0; s < NSTAGE - 1; s++) {
            const uint32_t st = sb + (uint32_t)s * STAGE;
            cpX(s, st); cpB(s, st); cp_commit();
        }
    } else {
        cpB(0, sb); cp_commit(); stXinline(sb);
    }

    for (int ch = 0; ch < NCHUNK; ch++) {
        const uint32_t st = sb + (uint32_t)(ch % NSTAGE) * STAGE;
        if constexpr (PIPE) {
            const int pf = ch + NSTAGE - 1;
            if (pf < NCHUNK) {
                const uint32_t st2 = sb + (uint32_t)(pf % NSTAGE) * STAGE;
                cpX(pf, st2); cpB(pf, st2);
            }
            cp_commit();
            cp_wait<NSTAGE - 1>();
        } else {
            cp_wait<0>();
        }
        __syncthreads();

#pragma unroll
        for (int ks = 0; ks < 4; ks++) {
            uint32_t aH[2][4], aL[2][4];
#pragma unroll
            for (int mt = 0; mt < 2; mt++) {
                uint32_t byte = (uint32_t)(wm + mt * 16 + (lane & 15)) * 128
                              + ks * 32 + (lane >> 4) * 16;
                uint32_t sw = sw128(byte);
                ldsm_x4(aH[mt], st + OXH + sw);
                ldsm_x4(aL[mt], st + OXL + sw);
            }
            uint32_t bH[NT][2], bL[NT][2];
#pragma unroll
            for (int nt = 0; nt < NT; nt++) {
                uint32_t byte = (uint32_t)(wn + nt * 8 + (lane & 7)) * 128
                              + ks * 32 + ((lane >> 3) & 1) * 16;
                uint32_t sw = sw128(byte);
                ldsm_x2(bH[nt], st + OBH + sw);
                ldsm_x2(bL[nt], st + OBL + sw);
            }
#pragma unroll
            for (int mt = 0; mt < 2; mt++)
#pragma unroll
                for (int nt = 0; nt < NT; nt++) {
                    mma16816(acc0[mt][nt], aH[mt], bH[nt]);   // independent
                    mma16816(acc1[mt][nt], aH[mt], bL[nt]);   // chains
                    mma16816(acc2[mt][nt], aL[mt], bH[nt]);
                }
        }
        __syncthreads();
    }

    // ---- epilogues (sum the three banks here) ----
#pragma unroll
    for (int mt = 0; mt < 2; mt++)
#pragma unroll
        for (int nt = 0; nt < NT; nt++) {
            const int r0  = m0 + wm + mt * 16 + (lane >> 2);
            const int col = n0 + wn + nt * 8 + (lane & 3) * 2;
#pragma unroll
            for (int half = 0; half < 2; half++) {
                const int row = r0 + half * 8;
                const float e0 = acc0[mt][nt][half*2]   + acc1[mt][nt][half*2]
                               + acc2[mt][nt][half*2];
                const float e1 = acc0[mt][nt][half*2+1] + acc1[mt][nt][half*2+1]
                               + acc2[mt][nt][half*2+1];
                const size_t idx = (size_t)row * NH + col;
                if constexpr (TMODE == TM_L1) {
                    float tv = pT[row];
                    float h0 = tanhf(e0 + tv * w1row[col]     + pC[col]);
                    float h1 = tanhf(e1 + tv * w1row[col + 1] + pC[col + 1]);
                    *(float2*)(g_h1 + idx) = make_float2(h0, h1);
                    store_split(g_h1s_h, g_h1s_l, idx, h0, h1);
                    float a0 = 1.f - h0 * h0, a1v = 1.f - h1 * h1;
                    store_split(g_a1s_h, g_a1s_l, idx, a0, a1v);
                    store_split(g_d1s_h, g_d1s_l, idx,
                                a0 * w1row[col], a1v * w1row[col + 1]);
                } else if constexpr (TMODE == TM_H2) {
                    if (zm == 0) {
                        float h0 = tanhf(e0 + pC[col]);
                        float h1 = tanhf(e1 + pC[col + 1]);
                        *(float2*)(g_h2 + idx) = make_float2(h0, h1);
                        store_split(g_a2s_h, g_a2s_l, idx,
                                    1.f - h0 * h0, 1.f - h1 * h1);
                    } else if (zm == 1) {
                        *(float2*)(g_r2 + idx) = make_float2(e0, e1);
                    } else {
                        *(float2*)(g_V + idx) = make_float2(e0, e1);
                    }
                } else if constexpr (TMODE == TM_QWU) {
                    float* o = zm ? g_r1 : g_U;
                    *(float2*)(o + idx) = make_float2(e0, e1);
                } else {  // TM_P
                    float2 h = *(const float2*)(g_h2 + idx);
                    float2 v = *(const float2*)(g_V + idx);
                    float w0 = (1.f - h.x * h.x) * (e0 - 2.f * h.x * v.x);
                    float w1 = (1.f - h.y * h.y) * (e1 - 2.f * h.y * v.y);
                    store_split(g_wbs_h, g_wbs_l, idx, w0, w1);
                }
            }
        }
}

// ---------------- thin SIMT GEMMs (N=64 outputs) ------------------------------
enum { M_S = 2, M_LOSS = 6 };

template<int MODE, int KDIM, int LDA, int LDB>
__global__ void __launch_bounds__(256)
gemm_k(const float* __restrict__ pB, const float* __restrict__ pC,
       const float* __restrict__ pD, float* __restrict__ pOut) {
    constexpr int BK = 32;
    __shared__ __align__(16) float Xs[BK][17];
    __shared__ __align__(16) float Bs[BK][68];
    const int tid = threadIdx.x;
    const int tx = tid & 15, ty = tid >> 4;
    const int m0 = blockIdx.y * 16;
    const float* Bg = (MODE == M_S) ? pB : g_W1T;

    float acc[4] = {0.f, 0.f, 0.f, 0.f};
    float stp = 0.f;
    const int lrow = tid >> 4;
    const int lkc  = (tid & 15) * 2;

    for (int k0 = 0; k0 < KDIM; k0 += BK) {
        {
            size_t idx = (size_t)(m0 + lrow) * LDA + k0 + lkc;
            if constexpr (MODE == M_S) {
                float2 v = *(const float2*)(g_h2 + idx);
                float2 z = *(const float2*)(g_r2 + idx);
                float2 w = *(const float2*)(g_w3s + k0 + lkc);
                stp += (1.f - v.x * v.x) * z.x * w.x
                     + (1.f - v.y * v.y) * z.y * w.y;
                Xs[lkc][lrow] = v.x; Xs[lkc + 1][lrow] = v.y;
            } else {
                float2 q = *(const float2*)(g_r1 + idx);
                float2 h = *(const float2*)(g_h1 + idx);
                float2 u = *(const float2*)(g_U + idx);
                float a0 = 1.f - h.x * h.x, a1v = 1.f - h.y * h.y;
                Xs[lkc][lrow]     = a0  * q.x - 2.f * h.x * a0  * u.x;
                Xs[lkc + 1][lrow] = a1v * q.y - 2.f * h.y * a1v * u.y;
            }
        }
        {
            int brow = tid >> 4, bnq = (tid & 15) * 4;
            *(float4*)&Bs[brow][bnq] =
                *(const float4*)(Bg + (size_t)(k0 + brow) * LDB + bnq);
            *(float4*)&Bs[brow + 16][bnq] =
                *(const float4*)(Bg + (size_t)(k0 + brow + 16) * LDB + bnq);
        }
        __syncthreads();
#pragma unroll
        for (int kk = 0; kk < BK; kk++) {
            float a = Xs[kk][ty];
            float4 b = *(const float4*)&Bs[kk][tx * 4];
            acc[0] += a * b.x; acc[1] += a * b.y;
            acc[2] += a * b.z; acc[3] += a * b.w;
        }
        __syncthreads();
    }
    const int row = m0 + ty, col = tx * 4;
    if constexpr (MODE == M_S) {
#pragma unroll
        for (int o = 8; o; o >>= 1)
            stp += __shfl_xor_sync(0xffffffffu, stp, o, 16);
        if ((tid & 15) == 0) g_st[m0 + lrow] = stp;
#pragma unroll
        for (int c = 0; c < 4; c++) {
            size_t idx = (size_t)row * ND + col + c;
            float sv = acc[c] + pC[col + c];
            g_s[idx] = sv;
            g_y[idx] = 2.f * sv + pD[idx];
        }
    } else {
        float stv = g_st[row], bet = pC[row];
        float ps = 0.f;
#pragma unroll
        for (int c = 0; c < 4; c++) {
            float g = acc[c] + g_s[(size_t)row * ND + col + c];
            ps += fabsf(stv - 0.5f * bet * g);
        }
#pragma unroll
        for (int o = 8; o; o >>= 1) ps += __shfl_xor_sync(0xffffffffu, ps, o);
        if (tx == 0) pOut[row] = ps * (1.f / 64.f);
    }
}

// ---------------- launch -----------------------------------------------------
#define SM_H2   (3 * (2 * 128 * 128 + 16384))   // 147456 (3-stage, BM=128)
#define SM_P64  (4 * (2 * 64 * 128 + 16384))    // 131072 (4-stage, BM=64)
#define SM_S64  (2 * 64 * 128 + 16384)          // 32768  (single-stage)

extern "C" void kernel_launch(void* const* d_in, const int* in_sizes, int n_in,
                              void* d_out, int out_size) {
    const float* x    = (const float*)d_in[0];
    const float* t    = (const float*)d_in[1];
    const float* beta = (const float*)d_in[2];
    const float* W1   = (const float*)d_in[3];
    const float* b1   = (const float*)d_in[4];
    const float* W2   = (const float*)d_in[5];
    const float* b2   = (const float*)d_in[6];
    const float* W3   = (const float*)d_in[7];
    const float* b3   = (const float*)d_in[8];
    float* out = (float*)d_out;
    const float* w1t = W1 + (size_t)ND * NH;   // W1 t-row

    cudaFuncSetAttribute(tmma<TM_L1, 64>,  cudaFuncAttributeMaxDynamicSharedMemorySize, SM_S64);
    cudaFuncSetAttribute(tmma<TM_H2, 128>, cudaFuncAttributeMaxDynamicSharedMemorySize, SM_H2);
    cudaFuncSetAttribute(tmma<TM_QWU, 64>, cudaFuncAttributeMaxDynamicSharedMemorySize, SM_P64);
    cudaFuncSetAttribute(tmma<TM_P, 64>,   cudaFuncAttributeMaxDynamicSharedMemorySize, SM_S64);

    dim3 gThin(1, NB/16);          // 64 blocks
    dim3 gT2  (NH/64, NB/128, 3);  // 192 blocks: {h2raw, z2, V}
    dim3 gQWU (NH/64, NB/64,  2);  // 256 blocks: {U, qw}
    dim3 gT64 (NH/64, NB/64);      // 128 blocks

    prep_kernel<<<dim3(NH/16, NH/16), dim3(16,16)>>>(W1, W2, W3);
    // h1 = tanh([x,t]@W1 + b1); writes h1, h1s, a1s, d1s
    tmma<TM_L1, 64><<<gT64, 256, SM_S64>>>(x, b1, t, w1t);
    // z0: h2 = tanh(h1@W2 + b2) (+a2s); z1: z2 = d1@W2; z2: V = a1@A
    tmma<TM_H2, 128><<<gT2, 256, SM_H2>>>(nullptr, b2, nullptr, nullptr);
    // s = h2@W3 + b3; y = 2s + x; s_t fused   (4th launch -> ncu target)
    gemm_k<M_S, NH, NH, ND><<<gThin, 256>>>(W3, b3, x, nullptr);
    // P = y@W3^T; wb = a2*(P - 2 h2 V) -> wbs
    tmma<TM_P, 64><<<gT64, 256, SM_S64>>>(nullptr, nullptr, nullptr, nullptr);
    // z0: U = a2@A'; z1: qw = wb@W2^T   (merged dual launch)
    tmma<TM_QWU, 64><<<gQWU, 256, SM_P64>>>(nullptr, nullptr, nullptr, nullptr);
    // c on the fly; G = c@W1x^T + s; loss
    gemm_k<M_LOSS, NH, NH, ND><<<gThin, 256>>>(nullptr, beta, nullptr, out);
}

// round 14
// speedup vs baseline: 1.1417x; 1.1379x over previous
#include <cuda_runtime.h>
#include <cuda_bf16.h>
#include <math.h>
#include <stdint.h>

#define NB 1024
#define ND 64
#define NH 512
#define KSPLIT 8

typedef __nv_bfloat16 bf16;

// ---------------- fp32 scratch ----------------
__device__ __align__(256) float g_W1T[NH*ND];   // [k,i] = W1[i,k]
__device__ __align__(256) float g_w3s[NH];
__device__ __align__(256) float g_h1 [NB*NH];
__device__ __align__(256) float g_h2 [NB*NH];
__device__ __align__(256) float g_U  [NB*NH];
__device__ __align__(256) float g_V  [NB*NH];
__device__ __align__(256) float g_r1 [NB*NH];   // qw
__device__ __align__(256) float g_r2 [NB*NH];   // z2
__device__ __align__(256) float g_s  [NB*ND];
__device__ __align__(256) float g_y  [NB*ND];
__device__ __align__(256) float g_st [NB];
__device__ __align__(256) float g_sp [KSPLIT*NB*ND];   // split-K partials (S)
__device__ __align__(256) float g_gp [KSPLIT*NB*ND];   // split-K partials (LOSS)
__device__ __align__(256) float g_stp[NB*KSPLIT];      // s_t partials

// ---------------- bf16 hi/lo pre-split scratch ----------------
__device__ __align__(256) bf16 g_W1Ts_h[NH*ND], g_W1Ts_l[NH*ND]; // [n,k]=W1[k,n]
__device__ __align__(256) bf16 g_W3s_h [NH*ND], g_W3s_l [NH*ND]; // [n,j]=W3[n,j]
__device__ __align__(256) bf16 g_W2Ts_h[NH*NH], g_W2Ts_l[NH*NH]; // [n,k]=W2[k,n]
__device__ __align__(256) bf16 g_W2s_h [NH*NH], g_W2s_l [NH*NH]; // [n,k]=W2[n,k]
__device__ __align__(256) bf16 g_As_h  [NH*NH], g_As_l  [NH*NH]; // [n,k]=A[n,k]
__device__ __align__(256) bf16 g_ATs_h [NH*NH], g_ATs_l [NH*NH]; // [n,k]=A[k,n]
__device__ __align__(256) bf16 g_h1s_h [NB*NH], g_h1s_l [NB*NH];
__device__ __align__(256) bf16 g_d1s_h [NB*NH], g_d1s_l [NB*NH];
__device__ __align__(256) bf16 g_a1s_h [NB*NH], g_a1s_l [NB*NH];
__device__ __align__(256) bf16 g_a2s_h [NB*NH], g_a2s_l [NB*NH];
__device__ __align__(256) bf16 g_wbs_h [NB*NH], g_wbs_l [NB*NH];

// ---------------- helpers ------------------------------------------------
__device__ __forceinline__ uint32_t smem_u32(const void* p) {
    return (uint32_t)__cvta_generic_to_shared(p);
}
__device__ __forceinline__ void sts_v2(uint32_t addr, uint32_t a, uint32_t b) {
    asm volatile("st.shared.v2.b32 [%0], {%1,%2};" :: "r"(addr), "r"(a), "r"(b));
}
__device__ __forceinline__ void cp16(uint32_t saddr, const void* gaddr) {
    asm volatile("cp.async.cg.shared.global [%0], [%1], 16;"
                 :: "r"(saddr), "l"(gaddr));
}
__device__ __forceinline__ void cp_commit() {
    asm volatile("cp.async.commit_group;" ::: "memory");
}
template<int N> __device__ __forceinline__ void cp_wait() {
    asm volatile("cp.async.wait_group %0;" :: "n"(N) : "memory");
}
__device__ __forceinline__ void split2(float x0, float x1, uint32_t& hi, uint32_t& lo) {
    bf16 h0 = __float2bfloat16(x0), h1 = __float2bfloat16(x1);
    bf16 l0 = __float2bfloat16(x0 - __bfloat162float(h0));
    bf16 l1 = __float2bfloat16(x1 - __bfloat162float(h1));
    __nv_bfloat162 H; H.x = h0; H.y = h1;
    __nv_bfloat162 L; L.x = l0; L.y = l1;
    hi = *reinterpret_cast<uint32_t*>(&H);
    lo = *reinterpret_cast<uint32_t*>(&L);
}
__device__ __forceinline__ void splitf(float v, bf16* H, bf16* L, size_t idx) {
    bf16 h = __float2bfloat16(v);
    H[idx] = h;
    L[idx] = __float2bfloat16(v - __bfloat162float(h));
}
__device__ __forceinline__ void store_split(bf16* H, bf16* L, size_t idx,
                                            float v0, float v1) {
    uint32_t hi, lo; split2(v0, v1, hi, lo);
    *reinterpret_cast<uint32_t*>(H + idx) = hi;
    *reinterpret_cast<uint32_t*>(L + idx) = lo;
}
__device__ __forceinline__ void ldsm_x4(uint32_t* r, uint32_t addr) {
    asm volatile("ldmatrix.sync.aligned.m8n8.x4.shared.b16 {%0,%1,%2,%3}, [%4];"
                 : "=r"(r[0]), "=r"(r[1]), "=r"(r[2]), "=r"(r[3]) : "r"(addr));
}
__device__ __forceinline__ void ldsm_x2(uint32_t* r, uint32_t addr) {
    asm volatile("ldmatrix.sync.aligned.m8n8.x2.shared.b16 {%0,%1}, [%2];"
                 : "=r"(r[0]), "=r"(r[1]) : "r"(addr));
}
__device__ __forceinline__ void mma16816(float* c, const uint32_t* a, const uint32_t* b) {
    asm volatile(
        "mma.sync.aligned.m16n8k16.row.col.f32.bf16.bf16.f32 "
        "{%0,%1,%2,%3}, {%4,%5,%6,%7}, {%8,%9}, {%0,%1,%2,%3};"
        : "+f"(c[0]), "+f"(c[1]), "+f"(c[2]), "+f"(c[3])
        : "r"(a[0]), "r"(a[1]), "r"(a[2]), "r"(a[3]), "r"(b[0]), "r"(b[1]));
}
__device__ __forceinline__ uint32_t sw128(uint32_t byte) {
    return byte ^ ((byte >> 3) & 0x70);
}

// ---------------- prep: weights + derived matrices, pre-split ----------------
__global__ void prep_kernel(const float* __restrict__ W1,
                            const float* __restrict__ W2,
                            const float* __restrict__ W3) {
    __shared__ float w2ts[16][17];
    const int tx = threadIdx.x, ty = threadIdx.y;
    const int r = blockIdx.y * 16 + ty;
    const int c = blockIdx.x * 16 + tx;
    w2ts[ty][tx] = W2[(size_t)(blockIdx.x * 16 + ty) * NH + blockIdx.y * 16 + tx];
    __syncthreads();
    float w2rc = W2[(size_t)r * NH + c];
    float w2cr = w2ts[tx][ty];
    float d1 = 0.f, d2 = 0.f;
#pragma unroll
    for (int i = 0; i < ND; i++) {
        d1 += W3[c * ND + i] * W1[i * NH + r];
        d2 += W3[r * ND + i] * W1[i * NH + c];
    }
    const size_t idx = (size_t)r * NH + c;
    splitf(w2rc,      g_W2s_h,  g_W2s_l,  idx);
    splitf(w2cr,      g_W2Ts_h, g_W2Ts_l, idx);
    splitf(w2rc * d1, g_As_h,   g_As_l,   idx);   // A[r,c]
    splitf(w2cr * d2, g_ATs_h,  g_ATs_l,  idx);   // A[c,r]
    if (c < ND) {
        float w1v = W1[c * NH + r];
        g_W1T[r * ND + c] = w1v;
        splitf(w1v,          g_W1Ts_h, g_W1Ts_l, (size_t)r * ND + c);
        splitf(W3[r*ND + c], g_W3s_h,  g_W3s_l,  (size_t)r * ND + c);
    }
    if (blockIdx.y == 0 && ty == 0) {
        float s1 = 0.f;
#pragma unroll
        for (int j = 0; j < ND; j++) s1 += W3[c * ND + j];
        g_w3s[c] = s1;
    }
}

// ---------------- tensor GEMMs -----------------------------------------------
enum { TM_L1 = 0, TM_H2 = 1, TM_QWU = 2, TM_P = 3 };

template<int TMODE, int BM>
__global__ void __launch_bounds__(256, 1)
tmma(const float* __restrict__ pX, const float* __restrict__ pC,
     const float* __restrict__ pT, const float* __restrict__ w1row) {
    extern __shared__ __align__(1024) char tsm[];
    const uint32_t sb = smem_u32(tsm);
    constexpr bool PIPE = (TMODE == TM_H2 || TMODE == TM_QWU);
    constexpr int NCHUNK = PIPE ? 8 : 1;
    constexpr int NSTAGE = PIPE ? ((BM == 128) ? 3 : 4) : 1;
    constexpr uint32_t XSZ = BM * 128;
    constexpr uint32_t OXH = 0, OXL = XSZ, OBH = 2 * XSZ, OBL = 2 * XSZ + 8192;
    constexpr uint32_t STAGE = 2 * XSZ + 16384;
    constexpr int NT = (BM == 128) ? 4 : 2;
    constexpr int LDBW = (TMODE == TM_L1 || TMODE == TM_P) ? ND : NH;

    const int tid = threadIdx.x, lane = tid & 31, wid = tid >> 5;
    const int zm = blockIdx.z;
    const int n0 = blockIdx.x * 64, m0 = blockIdx.y * BM;
    const int wm = (BM == 128 ? (wid & 3) : (wid & 1)) * 32;
    const int wn = (BM == 128 ? (wid >> 2) * 32 : (wid >> 1) * 16);

    const bf16 *Xh = nullptr, *Xl = nullptr;
    if constexpr (TMODE == TM_H2) {
        Xh = (zm == 0) ? g_h1s_h : (zm == 1) ? g_d1s_h : g_a1s_h;
        Xl = (zm == 0) ? g_h1s_l : (zm == 1) ? g_d1s_l : g_a1s_l;
    }
    else if constexpr (TMODE == TM_QWU) {
        Xh = zm ? g_wbs_h : g_a2s_h;
        Xl = zm ? g_wbs_l : g_a2s_l;
    }
    const bf16 *Bh, *Bl;
    if constexpr (TMODE == TM_L1)      { Bh = g_W1Ts_h; Bl = g_W1Ts_l; }
    else if constexpr (TMODE == TM_H2) {
        Bh = (zm <= 1) ? g_W2Ts_h : g_ATs_h;
        Bl = (zm <= 1) ? g_W2Ts_l : g_ATs_l;
    }
    else if constexpr (TMODE == TM_QWU) {
        Bh = zm ? g_W2s_h : g_As_h;
        Bl = zm ? g_W2s_l : g_As_l;
    }
    else { Bh = g_W3s_h; Bl = g_W3s_l; }

    const int xrow = (BM == 128) ? (tid >> 1) : (tid >> 2);
    const int xcb  = (BM == 128) ? ((tid & 1) * 32) : ((tid & 3) * 16);
    const int brow = tid >> 2, bcb = (tid & 3) * 16;

    auto cpX = [&](int ch, uint32_t st) {
        constexpr int NI = (BM == 128) ? 4 : 2;
        size_t base = (size_t)(m0 + xrow) * NH + ch * 64 + xcb;
#pragma unroll
        for (int i = 0; i < NI; i++) {
            int col = xcb + i * 8;
            uint32_t sw = sw128((uint32_t)xrow * 128 + col * 2);
            cp16(st + OXH + sw, Xh + base + i * 8);
            cp16(st + OXL + sw, Xl + base + i * 8);
        }
    };
    auto cpB = [&](int ch, uint32_t st) {
        size_t base = (size_t)(n0 + brow) * LDBW + (PIPE ? ch * 64 : 0) + bcb;
#pragma unroll
        for (int i = 0; i < 2; i++) {
            int col = bcb + i * 8;
            uint32_t sw = sw128((uint32_t)brow * 128 + col * 2);
            cp16(st + OBH + sw, Bh + base + i * 8);
            cp16(st + OBL + sw, Bl + base + i * 8);
        }
    };
    auto stXinline = [&](uint32_t st) {   // L1 / P only (BM=64, K=64 fp32)
        const int row = tid >> 2, cb = (tid & 3) * 16;
        const float* src = (TMODE == TM_L1) ? pX : g_y;
        const float* xr = src + (size_t)(m0 + row) * 64 + cb;
#pragma unroll
        for (int i = 0; i < 4; i++) {
            float4 v = *(const float4*)(xr + i * 4);
            uint32_t h01, l01, h23, l23;
            split2(v.x, v.y, h01, l01);
            split2(v.z, v.w, h23, l23);
            uint32_t sw = sw128((uint32_t)row * 128 + (cb + i * 4) * 2);
            sts_v2(st + OXH + sw, h01, h23);
            sts_v2(st + OXL + sw, l01, l23);
        }
    };

    float acc0[2][NT][4], acc1[2][NT][4], acc2[2][NT][4];
#pragma unroll
    for (int mt = 0; mt < 2; mt++)
#pragma unroll
        for (int nt = 0; nt < NT; nt++)
#pragma unroll
            for (int i = 0; i < 4; i++) {
                acc0[mt][nt][i] = 0.f;
                acc1[mt][nt][i] = 0.f;
                acc2[mt][nt][i] = 0.f;
            }

    if constexpr (PIPE) {
#pragma unroll
        for (int s = 0; s < NSTAGE - 1; s++) {
            const uint32_t st = sb + (uint32_t)s * STAGE;
            cpX(s, st); cpB(s, st); cp_commit();
        }
    } else {
        cpB(0, sb); cp_commit(); stXinline(sb);
    }

    for (int ch = 0; ch < NCHUNK; ch++) {
        const uint32_t st = sb + (uint32_t)(ch % NSTAGE) * STAGE;
        if constexpr (PIPE) {
            const int pf = ch + NSTAGE - 1;
            if (pf < NCHUNK) {
                const uint32_t st2 = sb + (uint32_t)(pf % NSTAGE) * STAGE;
                cpX(pf, st2); cpB(pf, st2);
            }
            cp_commit();
            cp_wait<NSTAGE - 1>();
        } else {
            cp_wait<0>();
        }
        __syncthreads();

#pragma unroll
        for (int ks = 0; ks < 4; ks++) {
            uint32_t aH[2][4], aL[2][4];
#pragma unroll
            for (int mt = 0; mt < 2; mt++) {
                uint32_t byte = (uint32_t)(wm + mt * 16 + (lane & 15)) * 128
                              + ks * 32 + (lane >> 4) * 16;
                uint32_t sw = sw128(byte);
                ldsm_x4(aH[mt], st + OXH + sw);
                ldsm_x4(aL[mt], st + OXL + sw);
            }
            uint32_t bH[NT][2], bL[NT][2];
#pragma unroll
            for (int nt = 0; nt < NT; nt++) {
                uint32_t byte = (uint32_t)(wn + nt * 8 + (lane & 7)) * 128
                              + ks * 32 + ((lane >> 3) & 1) * 16;
                uint32_t sw = sw128(byte);
                ldsm_x2(bH[nt], st + OBH + sw);
                ldsm_x2(bL[nt], st + OBL + sw);
            }
#pragma unroll
            for (int mt = 0; mt < 2; mt++)
#pragma unroll
                for (int nt = 0; nt < NT; nt++) {
                    mma16816(acc0[mt][nt], aH[mt], bH[nt]);
                    mma16816(acc1[mt][nt], aH[mt], bL[nt]);
                    mma16816(acc2[mt][nt], aL[mt], bH[nt]);
                }
        }
        __syncthreads();
    }

#pragma unroll
    for (int mt = 0; mt < 2; mt++)
#pragma unroll
        for (int nt = 0; nt < NT; nt++) {
            const int r0  = m0 + wm + mt * 16 + (lane >> 2);
            const int col = n0 + wn + nt * 8 + (lane & 3) * 2;
#pragma unroll
            for (int half = 0; half < 2; half++) {
                const int row = r0 + half * 8;
                const float e0 = acc0[mt][nt][half*2]   + acc1[mt][nt][half*2]
                               + acc2[mt][nt][half*2];
                const float e1 = acc0[mt][nt][half*2+1] + acc1[mt][nt][half*2+1]
                               + acc2[mt][nt][half*2+1];
                const size_t idx = (size_t)row * NH + col;
                if constexpr (TMODE == TM_L1) {
                    float tv = pT[row];
                    float h0 = tanhf(e0 + tv * w1row[col]     + pC[col]);
                    float h1 = tanhf(e1 + tv * w1row[col + 1] + pC[col + 1]);
                    *(float2*)(g_h1 + idx) = make_float2(h0, h1);
                    store_split(g_h1s_h, g_h1s_l, idx, h0, h1);
                    float a0 = 1.f - h0 * h0, a1v = 1.f - h1 * h1;
                    store_split(g_a1s_h, g_a1s_l, idx, a0, a1v);
                    store_split(g_d1s_h, g_d1s_l, idx,
                                a0 * w1row[col], a1v * w1row[col + 1]);
                } else if constexpr (TMODE == TM_H2) {
                    if (zm == 0) {
                        float h0 = tanhf(e0 + pC[col]);
                        float h1 = tanhf(e1 + pC[col + 1]);
                        *(float2*)(g_h2 + idx) = make_float2(h0, h1);
                        store_split(g_a2s_h, g_a2s_l, idx,
                                    1.f - h0 * h0, 1.f - h1 * h1);
                    } else if (zm == 1) {
                        *(float2*)(g_r2 + idx) = make_float2(e0, e1);
                    } else {
                        *(float2*)(g_V + idx) = make_float2(e0, e1);
                    }
                } else if constexpr (TMODE == TM_QWU) {
                    float* o = zm ? g_r1 : g_U;
                    *(float2*)(o + idx) = make_float2(e0, e1);
                } else {  // TM_P
                    float2 h = *(const float2*)(g_h2 + idx);
                    float2 v = *(const float2*)(g_V + idx);
                    float w0 = (1.f - h.x * h.x) * (e0 - 2.f * h.x * v.x);
                    float w1 = (1.f - h.y * h.y) * (e1 - 2.f * h.y * v.y);
                    store_split(g_wbs_h, g_wbs_l, idx, w0, w1);
                }
            }
        }
}

// ---------------- split-K thin GEMMs (512 blocks each) ------------------------
// grid (KSPLIT, NB/16): block = 16 rows x 64 cols partial over 64 k.
// B matrix selected DEVICE-SIDE (g_W1T is a __device__ symbol).
template<int LOSS>
__global__ void __launch_bounds__(256)
split_thin(const float* __restrict__ pB) {
    __shared__ __align__(16) float Xs[64][17];
    __shared__ __align__(16) float Bs[64][68];
    const int tid = threadIdx.x;
    const int tx = tid & 15, ty = tid >> 4;
    const int m0 = blockIdx.y * 16;
    const int kc = blockIdx.x * 64;
    const float* Bg = LOSS ? g_W1T : pB;   // device-side symbol selection

    float stp = 0.f;
    {   // X tile: 16 rows x 64 k
        const int row = tid >> 4, kq = (tid & 15) * 4;
        size_t idx = (size_t)(m0 + row) * NH + kc + kq;
        if constexpr (!LOSS) {
            float4 v = *(const float4*)(g_h2 + idx);
            float4 z = *(const float4*)(g_r2 + idx);
            float4 w = *(const float4*)(g_w3s + kc + kq);
            stp = (1.f - v.x*v.x) * z.x * w.x + (1.f - v.y*v.y) * z.y * w.y
                + (1.f - v.z*v.z) * z.z * w.z + (1.f - v.w*v.w) * z.w * w.w;
            Xs[kq][row] = v.x; Xs[kq+1][row] = v.y;
            Xs[kq+2][row] = v.z; Xs[kq+3][row] = v.w;
        } else {
            float4 q = *(const float4*)(g_r1 + idx);
            float4 h = *(const float4*)(g_h1 + idx);
            float4 u = *(const float4*)(g_U + idx);
            Xs[kq][row]   = (1.f - h.x*h.x) * (q.x - 2.f * h.x * u.x);
            Xs[kq+1][row] = (1.f - h.y*h.y) * (q.y - 2.f * h.y * u.y);
            Xs[kq+2][row] = (1.f - h.z*h.z) * (q.z - 2.f * h.z * u.z);
            Xs[kq+3][row] = (1.f - h.w*h.w) * (q.w - 2.f * h.w * u.w);
        }
    }
    {   // B tile: 64 k x 64 n (Bg row-major [512][64])
        const int brow = tid >> 2, bq = (tid & 3) * 16;
        const float* br = Bg + (size_t)(kc + brow) * ND + bq;
#pragma unroll
        for (int i = 0; i < 4; i++)
            *(float4*)&Bs[brow][bq + i * 4] = *(const float4*)(br + i * 4);
    }
    __syncthreads();

    float acc[4] = {0.f, 0.f, 0.f, 0.f};
#pragma unroll
    for (int kk = 0; kk < 64; kk++) {
        float a = Xs[kk][ty];
        float4 b = *(const float4*)&Bs[kk][tx * 4];
        acc[0] += a * b.x; acc[1] += a * b.y;
        acc[2] += a * b.z; acc[3] += a * b.w;
    }

    float* o = (LOSS ? g_gp : g_sp)
             + (size_t)blockIdx.x * NB * ND + (size_t)(m0 + ty) * ND + tx * 4;
    *(float4*)o = make_float4(acc[0], acc[1], acc[2], acc[3]);

    if constexpr (!LOSS) {
#pragma unroll
        for (int off = 8; off; off >>= 1)
            stp += __shfl_xor_sync(0xffffffffu, stp, off, 16);
        if ((tid & 15) == 0) g_stp[(size_t)(m0 + (tid >> 4)) * KSPLIT + blockIdx.x] = stp;
    }
}

// ---------------- reduce S: s = Σ sp + b3; y = 2s + x; s_t = Σ stp ------------
__global__ void __launch_bounds__(256)
reduce_s(const float* __restrict__ b3, const float* __restrict__ x) {
    const int tid = threadIdx.x;
    const size_t gi = (size_t)blockIdx.x * 256 + tid;   // element id
    const int col = (int)(gi & 63);
    float s = b3[col];
#pragma unroll
    for (int kp = 0; kp < KSPLIT; kp++) s += g_sp[(size_t)kp * NB * ND + gi];
    g_s[gi] = s;
    g_y[gi] = 2.f * s + x[gi];
    const size_t row0 = (size_t)blockIdx.x * 4;         // 256 elems = 4 rows
    if (tid < 4) {
        float st = 0.f;
#pragma unroll
        for (int kp = 0; kp < KSPLIT; kp++)
            st += g_stp[(row0 + tid) * KSPLIT + kp];
        g_st[row0 + tid] = st;
    }
}

// ---------------- reduce LOSS: out = mean |st - 0.5 beta (Σ gp + s)| ----------
__global__ void __launch_bounds__(256)
reduce_loss(const float* __restrict__ beta, float* __restrict__ out) {
    __shared__ float red[8];
    const int tid = threadIdx.x;
    const int row = blockIdx.x * 4 + (tid >> 6);
    const int col = tid & 63;
    const size_t idx = (size_t)row * ND + col;
    float g = g_s[idx];
#pragma unroll
    for (int kp = 0; kp < KSPLIT; kp++) g += g_gp[(size_t)kp * NB * ND + idx];
    float v = fabsf(g_st[row] - 0.5f * beta[row] * g);
#pragma unroll
    for (int o = 16; o; o >>= 1) v += __shfl_xor_sync(0xffffffffu, v, o);
    if ((tid & 31) == 0) red[tid >> 5] = v;
    __syncthreads();
    if (tid < 4)
        out[blockIdx.x * 4 + tid] = (red[tid*2] + red[tid*2+1]) * (1.f / 64.f);
}

// ---------------- launch -----------------------------------------------------
#define SM_H2   (3 * (2 * 128 * 128 + 16384))   // 147456 (3-stage, BM=128)
#define SM_P64  (4 * (2 * 64 * 128 + 16384))    // 131072 (4-stage, BM=64)
#define SM_S64  (2 * 64 * 128 + 16384)          // 32768  (single-stage)

extern "C" void kernel_launch(void* const* d_in, const int* in_sizes, int n_in,
                              void* d_out, int out_size) {
    const float* x    = (const float*)d_in[0];
    const float* t    = (const float*)d_in[1];
    const float* beta = (const float*)d_in[2];
    const float* W1   = (const float*)d_in[3];
    const float* b1   = (const float*)d_in[4];
    const float* W2   = (const float*)d_in[5];
    const float* b2   = (const float*)d_in[6];
    const float* W3   = (const float*)d_in[7];
    const float* b3   = (const float*)d_in[8];
    float* out = (float*)d_out;
    const float* w1t = W1 + (size_t)ND * NH;   // W1 t-row

    cudaFuncSetAttribute(tmma<TM_L1, 64>,  cudaFuncAttributeMaxDynamicSharedMemorySize, SM_S64);
    cudaFuncSetAttribute(tmma<TM_H2, 128>, cudaFuncAttributeMaxDynamicSharedMemorySize, SM_H2);
    cudaFuncSetAttribute(tmma<TM_QWU, 64>, cudaFuncAttributeMaxDynamicSharedMemorySize, SM_P64);
    cudaFuncSetAttribute(tmma<TM_P, 64>,   cudaFuncAttributeMaxDynamicSharedMemorySize, SM_S64);

    dim3 gSplit(KSPLIT, NB/16);    // 512 blocks
    dim3 gT2  (NH/64, NB/128, 3);  // 192 blocks: {h2raw, z2, V}
    dim3 gQWU (NH/64, NB/64,  2);  // 256 blocks: {U, qw}
    dim3 gT64 (NH/64, NB/64);      // 128 blocks

    prep_kernel<<<dim3(NH/16, NH/16), dim3(16,16)>>>(W1, W2, W3);
    // h1 = tanh([x,t]@W1 + b1); writes h1, h1s, a1s, d1s
    tmma<TM_L1, 64><<<gT64, 256, SM_S64>>>(x, b1, t, w1t);
    // z0: h2 = tanh(h1@W2 + b2) (+a2s); z1: z2 = d1@W2; z2: V = a1@A
    tmma<TM_H2, 128><<<gT2, 256, SM_H2>>>(nullptr, b2, nullptr, nullptr);
    // split-K partials of s = h2@W3 (+ s_t partials)  [4th launch -> ncu]
    split_thin<0><<<gSplit, 256>>>(W3);
    // s, y, s_t finalize
    reduce_s<<<NB*ND/256, 256>>>(b3, x);
    // P = y@W3^T; wb = a2*(P - 2 h2 V) -> wbs
    tmma<TM_P, 64><<<gT64, 256, SM_S64>>>(nullptr, nullptr, nullptr, nullptr);
    // z0: U = a2@A'; z1: qw = wb@W2^T
    tmma<TM_QWU, 64><<<gQWU, 256, SM_P64>>>(nullptr, nullptr, nullptr, nullptr);
    // split-K partials of G = c@W1x^T (c on the fly; W1T selected device-side)
    split_thin<1><<<gSplit, 256>>>(nullptr);
    // loss = mean |s_t - 0.5 beta (G + s)|
    reduce_loss<<<NB/4, 256>>>(beta, out);
}

// round 15
// speedup vs baseline: 1.1572x; 1.0137x over previous
#include <cuda_runtime.h>
#include <cuda_bf16.h>
#include <math.h>
#include <stdint.h>

#define NB 1024
#define ND 64
#define NH 512
#define KSPLIT 8

typedef __nv_bfloat16 bf16;

// ---------------- fp32 scratch ----------------
__device__ __align__(256) float g_W1T[NH*ND];   // [k,i] = W1[i,k]
__device__ __align__(256) float g_w3s[NH];
__device__ __align__(256) float g_h1 [NB*NH];
__device__ __align__(256) float g_h2 [NB*NH];
__device__ __align__(256) float g_U  [NB*NH];
__device__ __align__(256) float g_V  [NB*NH];
__device__ __align__(256) float g_r1 [NB*NH];   // qw
__device__ __align__(256) float g_r2 [NB*NH];   // z2
__device__ __align__(256) float g_s  [NB*ND];
__device__ __align__(256) float g_y  [NB*ND];
__device__ __align__(256) float g_st [NB];
__device__ __align__(256) float g_sp [KSPLIT*NB*ND];   // split-K partials (S)
__device__ __align__(256) float g_gp [KSPLIT*NB*ND];   // split-K partials (LOSS)
__device__ __align__(256) float g_stp[NB*KSPLIT];      // s_t partials

// ---------------- bf16 hi/lo pre-split scratch ----------------
__device__ __align__(256) bf16 g_W1Ts_h[NH*ND], g_W1Ts_l[NH*ND]; // [n,k]=W1[k,n]
__device__ __align__(256) bf16 g_W3s_h [NH*ND], g_W3s_l [NH*ND]; // [n,j]=W3[n,j]
__device__ __align__(256) bf16 g_W2Ts_h[NH*NH], g_W2Ts_l[NH*NH]; // [n,k]=W2[k,n]
__device__ __align__(256) bf16 g_W2s_h [NH*NH], g_W2s_l [NH*NH]; // [n,k]=W2[n,k]
__device__ __align__(256) bf16 g_As_h  [NH*NH], g_As_l  [NH*NH]; // [n,k]=A[n,k]
__device__ __align__(256) bf16 g_ATs_h [NH*NH], g_ATs_l [NH*NH]; // [n,k]=A[k,n]
__device__ __align__(256) bf16 g_h1s_h [NB*NH], g_h1s_l [NB*NH];
__device__ __align__(256) bf16 g_d1s_h [NB*NH], g_d1s_l [NB*NH];
__device__ __align__(256) bf16 g_a1s_h [NB*NH], g_a1s_l [NB*NH];
__device__ __align__(256) bf16 g_a2s_h [NB*NH], g_a2s_l [NB*NH];
__device__ __align__(256) bf16 g_wbs_h [NB*NH], g_wbs_l [NB*NH];

// ---------------- helpers ------------------------------------------------
__device__ __forceinline__ uint32_t smem_u32(const void* p) {
    return (uint32_t)__cvta_generic_to_shared(p);
}
__device__ __forceinline__ void sts_v2(uint32_t addr, uint32_t a, uint32_t b) {
    asm volatile("st.shared.v2.b32 [%0], {%1,%2};" :: "r"(addr), "r"(a), "r"(b));
}
__device__ __forceinline__ void cp16(uint32_t saddr, const void* gaddr) {
    asm volatile("cp.async.cg.shared.global [%0], [%1], 16;"
                 :: "r"(saddr), "l"(gaddr));
}
__device__ __forceinline__ void cp_commit() {
    asm volatile("cp.async.commit_group;" ::: "memory");
}
template<int N> __device__ __forceinline__ void cp_wait() {
    asm volatile("cp.async.wait_group %0;" :: "n"(N) : "memory");
}
__device__ __forceinline__ void split2(float x0, float x1, uint32_t& hi, uint32_t& lo) {
    bf16 h0 = __float2bfloat16(x0), h1 = __float2bfloat16(x1);
    bf16 l0 = __float2bfloat16(x0 - __bfloat162float(h0));
    bf16 l1 = __float2bfloat16(x1 - __bfloat162float(h1));
    __nv_bfloat162 H; H.x = h0; H.y = h1;
    __nv_bfloat162 L; L.x = l0; L.y = l1;
    hi = *reinterpret_cast<uint32_t*>(&H);
    lo = *reinterpret_cast<uint32_t*>(&L);
}
__device__ __forceinline__ void splitf(float v, bf16* H, bf16* L, size_t idx) {
    bf16 h = __float2bfloat16(v);
    H[idx] = h;
    L[idx] = __float2bfloat16(v - __bfloat162float(h));
}
__device__ __forceinline__ void store_split(bf16* H, bf16* L, size_t idx,
                                            float v0, float v1) {
    uint32_t hi, lo; split2(v0, v1, hi, lo);
    *reinterpret_cast<uint32_t*>(H + idx) = hi;
    *reinterpret_cast<uint32_t*>(L + idx) = lo;
}
__device__ __forceinline__ void ldsm_x4(uint32_t* r, uint32_t addr) {
    asm volatile("ldmatrix.sync.aligned.m8n8.x4.shared.b16 {%0,%1,%2,%3}, [%4];"
                 : "=r"(r[0]), "=r"(r[1]), "=r"(r[2]), "=r"(r[3]) : "r"(addr));
}
__device__ __forceinline__ void ldsm_x2(uint32_t* r, uint32_t addr) {
    asm volatile("ldmatrix.sync.aligned.m8n8.x2.shared.b16 {%0,%1}, [%2];"
                 : "=r"(r[0]), "=r"(r[1]) : "r"(addr));
}
__device__ __forceinline__ void mma16816(float* c, const uint32_t* a, const uint32_t* b) {
    asm volatile(
        "mma.sync.aligned.m16n8k16.row.col.f32.bf16.bf16.f32 "
        "{%0,%1,%2,%3}, {%4,%5,%6,%7}, {%8,%9}, {%0,%1,%2,%3};"
        : "+f"(c[0]), "+f"(c[1]), "+f"(c[2]), "+f"(c[3])
        : "r"(a[0]), "r"(a[1]), "r"(a[2]), "r"(a[3]), "r"(b[0]), "r"(b[1]));
}
__device__ __forceinline__ uint32_t sw128(uint32_t byte) {
    return byte ^ ((byte >> 3) & 0x70);
}

// ---------------- prep: weights + derived matrices, pre-split ----------------
__global__ void prep_kernel(const float* __restrict__ W1,
                            const float* __restrict__ W2,
                            const float* __restrict__ W3) {
    __shared__ float w2ts[16][17];
    const int tx = threadIdx.x, ty = threadIdx.y;
    const int r = blockIdx.y * 16 + ty;
    const int c = blockIdx.x * 16 + tx;
    w2ts[ty][tx] = W2[(size_t)(blockIdx.x * 16 + ty) * NH + blockIdx.y * 16 + tx];
    __syncthreads();
    float w2rc = W2[(size_t)r * NH + c];
    float w2cr = w2ts[tx][ty];
    float d1 = 0.f, d2 = 0.f;
#pragma unroll
    for (int i = 0; i < ND; i++) {
        d1 += W3[c * ND + i] * W1[i * NH + r];
        d2 += W3[r * ND + i] * W1[i * NH + c];
    }
    const size_t idx = (size_t)r * NH + c;
    splitf(w2rc,      g_W2s_h,  g_W2s_l,  idx);
    splitf(w2cr,      g_W2Ts_h, g_W2Ts_l, idx);
    splitf(w2rc * d1, g_As_h,   g_As_l,   idx);   // A[r,c]
    splitf(w2cr * d2, g_ATs_h,  g_ATs_l,  idx);   // A[c,r]
    if (c < ND) {
        float w1v = W1[c * NH + r];
        g_W1T[r * ND + c] = w1v;
        splitf(w1v,          g_W1Ts_h, g_W1Ts_l, (size_t)r * ND + c);
        splitf(W3[r*ND + c], g_W3s_h,  g_W3s_l,  (size_t)r * ND + c);
    }
    if (blockIdx.y == 0 && ty == 0) {
        float s1 = 0.f;
#pragma unroll
        for (int j = 0; j < ND; j++) s1 += W3[c * ND + j];
        g_w3s[c] = s1;
    }
}

// ---------------- tensor GEMMs -----------------------------------------------
enum { TM_L1 = 0, TM_H2 = 1, TM_QWU = 2, TM_P = 3 };

template<int TMODE, int BM>
__global__ void __launch_bounds__(256, 1)
tmma(const float* __restrict__ pX, const float* __restrict__ pC,
     const float* __restrict__ pT, const float* __restrict__ w1row) {
    extern __shared__ __align__(1024) char tsm[];
    const uint32_t sb = smem_u32(tsm);
    constexpr bool PIPE = (TMODE == TM_H2 || TMODE == TM_QWU);
    constexpr int NCHUNK = PIPE ? 8 : 1;
    constexpr int NSTAGE = PIPE ? ((BM == 128) ? 3 : 4) : 1;
    constexpr uint32_t XSZ = BM * 128;
    constexpr uint32_t OXH = 0, OXL = XSZ, OBH = 2 * XSZ, OBL = 2 * XSZ + 8192;
    constexpr uint32_t STAGE = 2 * XSZ + 16384;
    constexpr int NT = (BM == 128) ? 4 : 2;
    constexpr int LDBW = (TMODE == TM_L1 || TMODE == TM_P) ? ND : NH;

    const int tid = threadIdx.x, lane = tid & 31, wid = tid >> 5;
    const int zm = blockIdx.z;
    const int n0 = blockIdx.x * 64, m0 = blockIdx.y * BM;
    const int wm = (BM == 128 ? (wid & 3) : (wid & 1)) * 32;
    const int wn = (BM == 128 ? (wid >> 2) * 32 : (wid >> 1) * 16);

    const bf16 *Xh = nullptr, *Xl = nullptr;
    if constexpr (TMODE == TM_H2) {
        Xh = (zm == 0) ? g_h1s_h : (zm == 1) ? g_d1s_h : g_a1s_h;
        Xl = (zm == 0) ? g_h1s_l : (zm == 1) ? g_d1s_l : g_a1s_l;
    }
    else if constexpr (TMODE == TM_QWU) {
        Xh = zm ? g_wbs_h : g_a2s_h;
        Xl = zm ? g_wbs_l : g_a2s_l;
    }
    const bf16 *Bh, *Bl;
    if constexpr (TMODE == TM_L1)      { Bh = g_W1Ts_h; Bl = g_W1Ts_l; }
    else if constexpr (TMODE == TM_H2) {
        Bh = (zm <= 1) ? g_W2Ts_h : g_ATs_h;
        Bl = (zm <= 1) ? g_W2Ts_l : g_ATs_l;
    }
    else if constexpr (TMODE == TM_QWU) {
        Bh = zm ? g_W2s_h : g_As_h;
        Bl = zm ? g_W2s_l : g_As_l;
    }
    else { Bh = g_W3s_h; Bl = g_W3s_l; }

    const int xrow = (BM == 128) ? (tid >> 1) : (tid >> 2);
    const int xcb  = (BM == 128) ? ((tid & 1) * 32) : ((tid & 3) * 16);
    const int brow = tid >> 2, bcb = (tid & 3) * 16;

    auto cpX = [&](int ch, uint32_t st) {
        constexpr int NI = (BM == 128) ? 4 : 2;
        size_t base = (size_t)(m0 + xrow) * NH + ch * 64 + xcb;
#pragma unroll
        for (int i = 0; i < NI; i++) {
            int col = xcb + i * 8;
            uint32_t sw = sw128((uint32_t)xrow * 128 + col * 2);
            cp16(st + OXH + sw, Xh + base + i * 8);
            cp16(st + OXL + sw, Xl + base + i * 8);
        }
    };
    auto cpB = [&](int ch, uint32_t st) {
        size_t base = (size_t)(n0 + brow) * LDBW + (PIPE ? ch * 64 : 0) + bcb;
#pragma unroll
        for (int i = 0; i < 2; i++) {
            int col = bcb + i * 8;
            uint32_t sw = sw128((uint32_t)brow * 128 + col * 2);
            cp16(st + OBH + sw, Bh + base + i * 8);
            cp16(st + OBL + sw, Bl + base + i * 8);
        }
    };
    auto stXinline = [&](uint32_t st) {   // L1 / P only (BM=64, K=64 fp32)
        const int row = tid >> 2, cb = (tid & 3) * 16;
        const float* src = (TMODE == TM_L1) ? pX : g_y;
        const float* xr = src + (size_t)(m0 + row) * 64 + cb;
#pragma unroll
        for (int i = 0; i < 4; i++) {
            float4 v = *(const float4*)(xr + i * 4);
            uint32_t h01, l01, h23, l23;
            split2(v.x, v.y, h01, l01);
            split2(v.z, v.w, h23, l23);
            uint32_t sw = sw128((uint32_t)row * 128 + (cb + i * 4) * 2);
            sts_v2(st + OXH + sw, h01, h23);
            sts_v2(st + OXL + sw, l01, l23);
        }
    };

    float acc0[2][NT][4], acc1[2][NT][4], acc2[2][NT][4];
#pragma unroll
    for (int mt = 0; mt < 2; mt++)
#pragma unroll
        for (int nt = 0; nt < NT; nt++)
#pragma unroll
            for (int i = 0; i < 4; i++) {
                acc0[mt][nt][i] = 0.f;
                acc1[mt][nt][i] = 0.f;
                acc2[mt][nt][i] = 0.f;
            }

    if constexpr (PIPE) {
#pragma unroll
        for (int s = 0; s < NSTAGE - 1; s++) {
            const uint32_t st = sb + (uint32_t)s * STAGE;
            cpX(s, st); cpB(s, st); cp_commit();
        }
    } else {
        cpB(0, sb); cp_commit(); stXinline(sb);
    }

    for (int ch = 0; ch < NCHUNK; ch++) {
        const uint32_t st = sb + (uint32_t)(ch % NSTAGE) * STAGE;
        if constexpr (PIPE) {
            const int pf = ch + NSTAGE - 1;
            if (pf < NCHUNK) {
                const uint32_t st2 = sb + (uint32_t)(pf % NSTAGE) * STAGE;
                cpX(pf, st2); cpB(pf, st2);
            }
            cp_commit();
            cp_wait<NSTAGE - 1>();
        } else {
            cp_wait<0>();
        }
        __syncthreads();

#pragma unroll
        for (int ks = 0; ks < 4; ks++) {
            uint32_t aH[2][4], aL[2][4];
#pragma unroll
            for (int mt = 0; mt < 2; mt++) {
                uint32_t byte = (uint32_t)(wm + mt * 16 + (lane & 15)) * 128
                              + ks * 32 + (lane >> 4) * 16;
                uint32_t sw = sw128(byte);
                ldsm_x4(aH[mt], st + OXH + sw);
                ldsm_x4(aL[mt], st + OXL + sw);
            }
            uint32_t bH[NT][2], bL[NT][2];
#pragma unroll
            for (int nt = 0; nt < NT; nt++) {
                uint32_t byte = (uint32_t)(wn + nt * 8 + (lane & 7)) * 128
                              + ks * 32 + ((lane >> 3) & 1) * 16;
                uint32_t sw = sw128(byte);
                ldsm_x2(bH[nt], st + OBH + sw);
                ldsm_x2(bL[nt], st + OBL + sw);
            }
#pragma unroll
            for (int mt = 0; mt < 2; mt++)
#pragma unroll
                for (int nt = 0; nt < NT; nt++) {
                    mma16816(acc0[mt][nt], aH[mt], bH[nt]);
                    mma16816(acc1[mt][nt], aH[mt], bL[nt]);
                    mma16816(acc2[mt][nt], aL[mt], bH[nt]);
                }
        }
        __syncthreads();
    }

#pragma unroll
    for (int mt = 0; mt < 2; mt++)
#pragma unroll
        for (int nt = 0; nt < NT; nt++) {
            const int r0  = m0 + wm + mt * 16 + (lane >> 2);
            const int col = n0 + wn + nt * 8 + (lane & 3) * 2;
#pragma unroll
            for (int half = 0; half < 2; half++) {
                const int row = r0 + half * 8;
                const float e0 = acc0[mt][nt][half*2]   + acc1[mt][nt][half*2]
                               + acc2[mt][nt][half*2];
                const float e1 = acc0[mt][nt][half*2+1] + acc1[mt][nt][half*2+1]
                               + acc2[mt][nt][half*2+1];
                const size_t idx = (size_t)row * NH + col;
                if constexpr (TMODE == TM_L1) {
                    float tv = pT[row];
                    float h0 = tanhf(e0 + tv * w1row[col]     + pC[col]);
                    float h1 = tanhf(e1 + tv * w1row[col + 1] + pC[col + 1]);
                    *(float2*)(g_h1 + idx) = make_float2(h0, h1);
                    store_split(g_h1s_h, g_h1s_l, idx, h0, h1);
                    float a0 = 1.f - h0 * h0, a1v = 1.f - h1 * h1;
                    store_split(g_a1s_h, g_a1s_l, idx, a0, a1v);
                    store_split(g_d1s_h, g_d1s_l, idx,
                                a0 * w1row[col], a1v * w1row[col + 1]);
                } else if constexpr (TMODE == TM_H2) {
                    if (zm == 0) {
                        float h0 = tanhf(e0 + pC[col]);
                        float h1 = tanhf(e1 + pC[col + 1]);
                        *(float2*)(g_h2 + idx) = make_float2(h0, h1);
                        store_split(g_a2s_h, g_a2s_l, idx,
                                    1.f - h0 * h0, 1.f - h1 * h1);
                    } else if (zm == 1) {
                        *(float2*)(g_r2 + idx) = make_float2(e0, e1);
                    } else {
                        *(float2*)(g_V + idx) = make_float2(e0, e1);
                    }
                } else if constexpr (TMODE == TM_QWU) {
                    float* o = zm ? g_r1 : g_U;
                    *(float2*)(o + idx) = make_float2(e0, e1);
                } else {  // TM_P
                    float2 h = *(const float2*)(g_h2 + idx);
                    float2 v = *(const float2*)(g_V + idx);
                    float w0 = (1.f - h.x * h.x) * (e0 - 2.f * h.x * v.x);
                    float w1 = (1.f - h.y * h.y) * (e1 - 2.f * h.y * v.y);
                    store_split(g_wbs_h, g_wbs_l, idx, w0, w1);
                }
            }
        }
}

// ---------------- split-K thin GEMMs (256 blocks, 128 thr) --------------------
// grid (KSPLIT, NB/32): block = 32 rows x 64 cols partial over 64 k.
// Each thread computes 2 rows x 8 cols (16 FFMA per k-iter, ratio 4.0).
template<int LOSS>
__global__ void __launch_bounds__(128)
split_thin(const float* __restrict__ pB) {
    __shared__ __align__(16) float Xs[64][33];
    __shared__ __align__(16) float Bs[64][68];
    const int tid = threadIdx.x;
    const int m0 = blockIdx.y * 32;
    const int kc = blockIdx.x * 64;
    const float* Bg = LOSS ? g_W1T : pB;   // device-side symbol selection

    float stp = 0.f;
    {   // X tile: 32 rows x 64 k; 128 threads, 4 float4 each
        const int row = tid >> 2, kq = (tid & 3) * 16;
        size_t idx = (size_t)(m0 + row) * NH + kc + kq;
#pragma unroll
        for (int i = 0; i < 4; i++) {
            const int kcol = kq + i * 4;
            if constexpr (!LOSS) {
                float4 v = *(const float4*)(g_h2 + idx + i * 4);
                float4 z = *(const float4*)(g_r2 + idx + i * 4);
                float4 w = *(const float4*)(g_w3s + kc + kcol);
                stp += (1.f - v.x*v.x) * z.x * w.x + (1.f - v.y*v.y) * z.y * w.y
                     + (1.f - v.z*v.z) * z.z * w.z + (1.f - v.w*v.w) * z.w * w.w;
                Xs[kcol][row] = v.x; Xs[kcol+1][row] = v.y;
                Xs[kcol+2][row] = v.z; Xs[kcol+3][row] = v.w;
            } else {
                float4 q = *(const float4*)(g_r1 + idx + i * 4);
                float4 h = *(const float4*)(g_h1 + idx + i * 4);
                float4 u = *(const float4*)(g_U + idx + i * 4);
                Xs[kcol][row]   = (1.f - h.x*h.x) * (q.x - 2.f * h.x * u.x);
                Xs[kcol+1][row] = (1.f - h.y*h.y) * (q.y - 2.f * h.y * u.y);
                Xs[kcol+2][row] = (1.f - h.z*h.z) * (q.z - 2.f * h.z * u.z);
                Xs[kcol+3][row] = (1.f - h.w*h.w) * (q.w - 2.f * h.w * u.w);
            }
        }
    }
    {   // B tile: 64 k x 64 n; 128 threads, 8 float4 each
        const int brow = tid >> 1, bq = (tid & 1) * 32;
        const float* br = Bg + (size_t)(kc + brow) * ND + bq;
#pragma unroll
        for (int i = 0; i < 8; i++)
            *(float4*)&Bs[brow][bq + i * 4] = *(const float4*)(br + i * 4);
    }
    __syncthreads();

    // compute mapping: ty = rows pair (0..15), tx = col group (0..7)
    const int ty = tid >> 3, tx = tid & 7;
    const int r0 = 2 * ty, r1 = 2 * ty + 1;
    float acc[2][8];
#pragma unroll
    for (int r = 0; r < 2; r++)
#pragma unroll
        for (int c = 0; c < 8; c++) acc[r][c] = 0.f;

#pragma unroll
    for (int kk = 0; kk < 64; kk++) {
        float a0 = Xs[kk][r0], a1 = Xs[kk][r1];
        float4 b0 = *(const float4*)&Bs[kk][tx * 8];
        float4 b1 = *(const float4*)&Bs[kk][tx * 8 + 4];
        acc[0][0] += a0 * b0.x; acc[0][1] += a0 * b0.y;
        acc[0][2] += a0 * b0.z; acc[0][3] += a0 * b0.w;
        acc[0][4] += a0 * b1.x; acc[0][5] += a0 * b1.y;
        acc[0][6] += a0 * b1.z; acc[0][7] += a0 * b1.w;
        acc[1][0] += a1 * b0.x; acc[1][1] += a1 * b0.y;
        acc[1][2] += a1 * b0.z; acc[1][3] += a1 * b0.w;
        acc[1][4] += a1 * b1.x; acc[1][5] += a1 * b1.y;
        acc[1][6] += a1 * b1.z; acc[1][7] += a1 * b1.w;
    }

    float* ob = (LOSS ? g_gp : g_sp) + (size_t)blockIdx.x * NB * ND;
#pragma unroll
    for (int r = 0; r < 2; r++) {
        float* o = ob + (size_t)(m0 + 2 * ty + r) * ND + tx * 8;
        *(float4*)o       = make_float4(acc[r][0], acc[r][1], acc[r][2], acc[r][3]);
        *(float4*)(o + 4) = make_float4(acc[r][4], acc[r][5], acc[r][6], acc[r][7]);
    }

    if constexpr (!LOSS) {
        // reduce stp across the 4 loader threads of each row (tid>>2 groups)
#pragma unroll
        for (int off = 2; off; off >>= 1)
            stp += __shfl_xor_sync(0xffffffffu, stp, off, 4);
        if ((tid & 3) == 0)
            g_stp[(size_t)(m0 + (tid >> 2)) * KSPLIT + blockIdx.x] = stp;
    }
}

// ---------------- reduce S: s = Σ sp + b3; y = 2s + x; s_t = Σ stp ------------
__global__ void __launch_bounds__(256)
reduce_s(const float* __restrict__ b3, const float* __restrict__ x) {
    const int tid = threadIdx.x;
    const size_t gi = (size_t)blockIdx.x * 256 + tid;   // element id
    const int col = (int)(gi & 63);
    float s = b3[col];
#pragma unroll
    for (int kp = 0; kp < KSPLIT; kp++) s += g_sp[(size_t)kp * NB * ND + gi];
    g_s[gi] = s;
    g_y[gi] = 2.f * s + x[gi];
    const size_t row0 = (size_t)blockIdx.x * 4;         // 256 elems = 4 rows
    if (tid < 4) {
        float st = 0.f;
#pragma unroll
        for (int kp = 0; kp < KSPLIT; kp++)
            st += g_stp[(row0 + tid) * KSPLIT + kp];
        g_st[row0 + tid] = st;
    }
}

// ---------------- reduce LOSS: out = mean |st - 0.5 beta (Σ gp + s)| ----------
__global__ void __launch_bounds__(256)
reduce_loss(const float* __restrict__ beta, float* __restrict__ out) {
    __shared__ float red[8];
    const int tid = threadIdx.x;
    const int row = blockIdx.x * 4 + (tid >> 6);
    const int col = tid & 63;
    const size_t idx = (size_t)row * ND + col;
    float g = g_s[idx];
#pragma unroll
    for (int kp = 0; kp < KSPLIT; kp++) g += g_gp[(size_t)kp * NB * ND + idx];
    float v = fabsf(g_st[row] - 0.5f * beta[row] * g);
#pragma unroll
    for (int o = 16; o; o >>= 1) v += __shfl_xor_sync(0xffffffffu, v, o);
    if ((tid & 31) == 0) red[tid >> 5] = v;
    __syncthreads();
    if (tid < 4)
        out[blockIdx.x * 4 + tid] = (red[tid*2] + red[tid*2+1]) * (1.f / 64.f);
}

// ---------------- launch -----------------------------------------------------
#define SM_H2   (3 * (2 * 128 * 128 + 16384))   // 147456 (3-stage, BM=128)
#define SM_P64  (4 * (2 * 64 * 128 + 16384))    // 131072 (4-stage, BM=64)
#define SM_S64  (2 * 64 * 128 + 16384)          // 32768  (single-stage)

extern "C" void kernel_launch(void* const* d_in, const int* in_sizes, int n_in,
                              void* d_out, int out_size) {
    const float* x    = (const float*)d_in[0];
    const float* t    = (const float*)d_in[1];
    const float* beta = (const float*)d_in[2];
    const float* W1   = (const float*)d_in[3];
    const float* b1   = (const float*)d_in[4];
    const float* W2   = (const float*)d_in[5];
    const float* b2   = (const float*)d_in[6];
    const float* W3   = (const float*)d_in[7];
    const float* b3   = (const float*)d_in[8];
    float* out = (float*)d_out;
    const float* w1t = W1 + (size_t)ND * NH;   // W1 t-row

    cudaFuncSetAttribute(tmma<TM_L1, 64>,  cudaFuncAttributeMaxDynamicSharedMemorySize, SM_S64);
    cudaFuncSetAttribute(tmma<TM_H2, 128>, cudaFuncAttributeMaxDynamicSharedMemorySize, SM_H2);
    cudaFuncSetAttribute(tmma<TM_QWU, 64>, cudaFuncAttributeMaxDynamicSharedMemorySize, SM_P64);
    cudaFuncSetAttribute(tmma<TM_P, 64>,   cudaFuncAttributeMaxDynamicSharedMemorySize, SM_S64);

    dim3 gSplit(KSPLIT, NB/32);    // 256 blocks, 128 threads
    dim3 gT2  (NH/64, NB/128, 3);  // 192 blocks: {h2raw, z2, V}
    dim3 gQWU (NH/64, NB/64,  2);  // 256 blocks: {U, qw}
    dim3 gT64 (NH/64, NB/64);      // 128 blocks

    prep_kernel<<<dim3(NH/16, NH/16), dim3(16,16)>>>(W1, W2, W3);
    // h1 = tanh([x,t]@W1 + b1); writes h1, h1s, a1s, d1s
    tmma<TM_L1, 64><<<gT64, 256, SM_S64>>>(x, b1, t, w1t);
    // z0: h2 = tanh(h1@W2 + b2) (+a2s); z1: z2 = d1@W2; z2: V = a1@A
    tmma<TM_H2, 128><<<gT2, 256, SM_H2>>>(nullptr, b2, nullptr, nullptr);
    // split-K partials of s = h2@W3 (+ s_t partials)  [4th launch -> ncu]
    split_thin<0><<<gSplit, 128>>>(W3);
    // s, y, s_t finalize
    reduce_s<<<NB*ND/256, 256>>>(b3, x);
    // P = y@W3^T; wb = a2*(P - 2 h2 V) -> wbs
    tmma<TM_P, 64><<<gT64, 256, SM_S64>>>(nullptr, nullptr, nullptr, nullptr);
    // z0: U = a2@A'; z1: qw = wb@W2^T
    tmma<TM_QWU, 64><<<gQWU, 256, SM_P64>>>(nullptr, nullptr, nullptr, nullptr);
    // split-K partials of G = c@W1x^T (c on the fly; W1T selected device-side)
    split_thin<1><<<gSplit, 128>>>(nullptr);
    // loss = mean |s_t - 0.5 beta (G + s)|
    reduce_loss<<<NB/4, 256>>>(beta, out);
}

// round 16
// speedup vs baseline: 1.1992x; 1.0362x over previous
#include <cuda_runtime.h>
#include <cuda_bf16.h>
#include <math.h>
#include <stdint.h>

#define NB 1024
#define ND 64
#define NH 512
#define KSPLIT 8

typedef __nv_bfloat16 bf16;

// ---------------- fp32 scratch ----------------
__device__ __align__(256) float g_W1T[NH*ND];   // [k,i] = W1[i,k]
__device__ __align__(256) float g_w3s[NH];
__device__ __align__(256) float g_h1 [NB*NH];
__device__ __align__(256) float g_h2 [NB*NH];
__device__ __align__(256) float g_U  [NB*NH];
__device__ __align__(256) float g_V  [NB*NH];
__device__ __align__(256) float g_r1 [NB*NH];   // qw
__device__ __align__(256) float g_r2 [NB*NH];   // z2
__device__ __align__(256) float g_s  [NB*ND];
__device__ __align__(256) float g_y  [NB*ND];
__device__ __align__(256) float g_st [NB];
__device__ __align__(256) float g_sp [KSPLIT*NB*ND];   // split-K partials (S)
__device__ __align__(256) float g_gp [KSPLIT*NB*ND];   // split-K partials (LOSS)
__device__ __align__(256) float g_stp[NB*KSPLIT];      // s_t partials

// ---------------- bf16 hi/lo pre-split scratch ----------------
__device__ __align__(256) bf16 g_W1Ts_h[NH*ND], g_W1Ts_l[NH*ND]; // [n,k]=W1[k,n]
__device__ __align__(256) bf16 g_W3s_h [NH*ND], g_W3s_l [NH*ND]; // [n,j]=W3[n,j]
__device__ __align__(256) bf16 g_W1xs_h[ND*NH], g_W1xs_l[ND*NH]; // [j,k]=W1[j,k] (x rows)
__device__ __align__(256) bf16 g_W3Ts_h[ND*NH], g_W3Ts_l[ND*NH]; // [n,k]=W3[k,n]
__device__ __align__(256) bf16 g_W2Ts_h[NH*NH], g_W2Ts_l[NH*NH]; // [n,k]=W2[k,n]
__device__ __align__(256) bf16 g_W2s_h [NH*NH], g_W2s_l [NH*NH]; // [n,k]=W2[n,k]
__device__ __align__(256) bf16 g_As_h  [NH*NH], g_As_l  [NH*NH]; // [n,k]=A[n,k]
__device__ __align__(256) bf16 g_ATs_h [NH*NH], g_ATs_l [NH*NH]; // [n,k]=A[k,n]
__device__ __align__(256) bf16 g_h1s_h [NB*NH], g_h1s_l [NB*NH];
__device__ __align__(256) bf16 g_d1s_h [NB*NH], g_d1s_l [NB*NH];
__device__ __align__(256) bf16 g_a1s_h [NB*NH], g_a1s_l [NB*NH];
__device__ __align__(256) bf16 g_a2s_h [NB*NH], g_a2s_l [NB*NH];
__device__ __align__(256) bf16 g_wbs_h [NB*NH], g_wbs_l [NB*NH];

// ---------------- helpers ------------------------------------------------
__device__ __forceinline__ uint32_t smem_u32(const void* p) {
    return (uint32_t)__cvta_generic_to_shared(p);
}
__device__ __forceinline__ void sts_v2(uint32_t addr, uint32_t a, uint32_t b) {
    asm volatile("st.shared.v2.b32 [%0], {%1,%2};" :: "r"(addr), "r"(a), "r"(b));
}
__device__ __forceinline__ void cp16(uint32_t saddr, const void* gaddr) {
    asm volatile("cp.async.cg.shared.global [%0], [%1], 16;"
                 :: "r"(saddr), "l"(gaddr));
}
__device__ __forceinline__ void cp_commit() {
    asm volatile("cp.async.commit_group;" ::: "memory");
}
template<int N> __device__ __forceinline__ void cp_wait() {
    asm volatile("cp.async.wait_group %0;" :: "n"(N) : "memory");
}
__device__ __forceinline__ void split2(float x0, float x1, uint32_t& hi, uint32_t& lo) {
    bf16 h0 = __float2bfloat16(x0), h1 = __float2bfloat16(x1);
    bf16 l0 = __float2bfloat16(x0 - __bfloat162float(h0));
    bf16 l1 = __float2bfloat16(x1 - __bfloat162float(h1));
    __nv_bfloat162 H; H.x = h0; H.y = h1;
    __nv_bfloat162 L; L.x = l0; L.y = l1;
    hi = *reinterpret_cast<uint32_t*>(&H);
    lo = *reinterpret_cast<uint32_t*>(&L);
}
__device__ __forceinline__ void splitf(float v, bf16* H, bf16* L, size_t idx) {
    bf16 h = __float2bfloat16(v);
    H[idx] = h;
    L[idx] = __float2bfloat16(v - __bfloat162float(h));
}
__device__ __forceinline__ void store_split(bf16* H, bf16* L, size_t idx,
                                            float v0, float v1) {
    uint32_t hi, lo; split2(v0, v1, hi, lo);
    *reinterpret_cast<uint32_t*>(H + idx) = hi;
    *reinterpret_cast<uint32_t*>(L + idx) = lo;
}
__device__ __forceinline__ void ldsm_x4(uint32_t* r, uint32_t addr) {
    asm volatile("ldmatrix.sync.aligned.m8n8.x4.shared.b16 {%0,%1,%2,%3}, [%4];"
                 : "=r"(r[0]), "=r"(r[1]), "=r"(r[2]), "=r"(r[3]) : "r"(addr));
}
__device__ __forceinline__ void ldsm_x2(uint32_t* r, uint32_t addr) {
    asm volatile("ldmatrix.sync.aligned.m8n8.x2.shared.b16 {%0,%1}, [%2];"
                 : "=r"(r[0]), "=r"(r[1]) : "r"(addr));
}
__device__ __forceinline__ void mma16816(float* c, const uint32_t* a, const uint32_t* b) {
    asm volatile(
        "mma.sync.aligned.m16n8k16.row.col.f32.bf16.bf16.f32 "
        "{%0,%1,%2,%3}, {%4,%5,%6,%7}, {%8,%9}, {%0,%1,%2,%3};"
        : "+f"(c[0]), "+f"(c[1]), "+f"(c[2]), "+f"(c[3])
        : "r"(a[0]), "r"(a[1]), "r"(a[2]), "r"(a[3]), "r"(b[0]), "r"(b[1]));
}
__device__ __forceinline__ uint32_t sw128(uint32_t byte) {
    return byte ^ ((byte >> 3) & 0x70);
}

// ---------------- prep: weights + derived matrices, pre-split ----------------
__global__ void prep_kernel(const float* __restrict__ W1,
                            const float* __restrict__ W2,
                            const float* __restrict__ W3) {
    __shared__ float w2ts[16][17];
    const int tx = threadIdx.x, ty = threadIdx.y;
    const int r = blockIdx.y * 16 + ty;
    const int c = blockIdx.x * 16 + tx;
    w2ts[ty][tx] = W2[(size_t)(blockIdx.x * 16 + ty) * NH + blockIdx.y * 16 + tx];
    __syncthreads();
    float w2rc = W2[(size_t)r * NH + c];
    float w2cr = w2ts[tx][ty];
    float d1 = 0.f, d2 = 0.f;
#pragma unroll
    for (int i = 0; i < ND; i++) {
        d1 += W3[c * ND + i] * W1[i * NH + r];
        d2 += W3[r * ND + i] * W1[i * NH + c];
    }
    const size_t idx = (size_t)r * NH + c;
    splitf(w2rc,      g_W2s_h,  g_W2s_l,  idx);
    splitf(w2cr,      g_W2Ts_h, g_W2Ts_l, idx);
    splitf(w2rc * d1, g_As_h,   g_As_l,   idx);   // A[r,c]
    splitf(w2cr * d2, g_ATs_h,  g_ATs_l,  idx);   // A[c,r]
    if (c < ND) {
        float w1v = W1[c * NH + r];
        g_W1T[r * ND + c] = w1v;
        splitf(w1v,          g_W1Ts_h, g_W1Ts_l, (size_t)r * ND + c);
        splitf(W3[r*ND + c], g_W3s_h,  g_W3s_l,  (size_t)r * ND + c);
    }
    if (blockIdx.x < 4) {
        // [j<64, k<512] layouts, coalesced stores
        const int j = blockIdx.x * 16 + ty;        // 0..63
        const int k = blockIdx.y * 16 + tx;        // 0..511
        splitf(W1[(size_t)j * NH + k], g_W1xs_h, g_W1xs_l, (size_t)j * NH + k);
        splitf(W3[(size_t)k * ND + j], g_W3Ts_h, g_W3Ts_l, (size_t)j * NH + k);
    }
    if (blockIdx.y == 0 && ty == 0) {
        float s1 = 0.f;
#pragma unroll
        for (int jj = 0; jj < ND; jj++) s1 += W3[c * ND + jj];
        g_w3s[c] = s1;
    }
}

// ---------------- tensor GEMMs -----------------------------------------------
enum { TM_L1 = 0, TM_H2 = 1, TM_QWU = 2, TM_P = 3 };

template<int TMODE, int BM>
__global__ void __launch_bounds__(256, 1)
tmma(const float* __restrict__ pX, const float* __restrict__ pC,
     const float* __restrict__ pT, const float* __restrict__ w1row) {
    extern __shared__ __align__(1024) char tsm[];
    const uint32_t sb = smem_u32(tsm);
    constexpr bool PIPE = (TMODE == TM_H2 || TMODE == TM_QWU);
    constexpr int NCHUNK = PIPE ? 8 : 1;
    constexpr int NSTAGE = PIPE ? ((BM == 128) ? 3 : 4) : 1;
    constexpr uint32_t XSZ = BM * 128;
    constexpr uint32_t OXH = 0, OXL = XSZ, OBH = 2 * XSZ, OBL = 2 * XSZ + 8192;
    constexpr uint32_t STAGE = 2 * XSZ + 16384;
    constexpr int NT = (BM == 128) ? 4 : 2;
    constexpr int LDBW = (TMODE == TM_L1 || TMODE == TM_P) ? ND : NH;

    const int tid = threadIdx.x, lane = tid & 31, wid = tid >> 5;
    const int zm = blockIdx.z;
    const int n0 = blockIdx.x * 64, m0 = blockIdx.y * BM;
    const int wm = (BM == 128 ? (wid & 3) : (wid & 1)) * 32;
    const int wn = (BM == 128 ? (wid >> 2) * 32 : (wid >> 1) * 16);

    const bf16 *Xh = nullptr, *Xl = nullptr;
    if constexpr (TMODE == TM_H2) {
        Xh = (zm == 0) ? g_h1s_h : (zm == 1) ? g_d1s_h : g_a1s_h;
        Xl = (zm == 0) ? g_h1s_l : (zm == 1) ? g_d1s_l : g_a1s_l;
    }
    else if constexpr (TMODE == TM_QWU) {
        Xh = zm ? g_wbs_h : g_a2s_h;
        Xl = zm ? g_wbs_l : g_a2s_l;
    }
    const bf16 *Bh, *Bl;
    if constexpr (TMODE == TM_L1)      { Bh = g_W1Ts_h; Bl = g_W1Ts_l; }
    else if constexpr (TMODE == TM_H2) {
        Bh = (zm <= 1) ? g_W2Ts_h : g_ATs_h;
        Bl = (zm <= 1) ? g_W2Ts_l : g_ATs_l;
    }
    else if constexpr (TMODE == TM_QWU) {
        Bh = zm ? g_W2s_h : g_As_h;
        Bl = zm ? g_W2s_l : g_As_l;
    }
    else { Bh = g_W3s_h; Bl = g_W3s_l; }

    const int xrow = (BM == 128) ? (tid >> 1) : (tid >> 2);
    const int xcb  = (BM == 128) ? ((tid & 1) * 32) : ((tid & 3) * 16);
    const int brow = tid >> 2, bcb = (tid & 3) * 16;

    auto cpX = [&](int ch, uint32_t st) {
        constexpr int NI = (BM == 128) ? 4 : 2;
        size_t base = (size_t)(m0 + xrow) * NH + ch * 64 + xcb;
#pragma unroll
        for (int i = 0; i < NI; i++) {
            int col = xcb + i * 8;
            uint32_t sw = sw128((uint32_t)xrow * 128 + col * 2);
            cp16(st + OXH + sw, Xh + base + i * 8);
            cp16(st + OXL + sw, Xl + base + i * 8);
        }
    };
    auto cpB = [&](int ch, uint32_t st) {
        size_t base = (size_t)(n0 + brow) * LDBW + (PIPE ? ch * 64 : 0) + bcb;
#pragma unroll
        for (int i = 0; i < 2; i++) {
            int col = bcb + i * 8;
            uint32_t sw = sw128((uint32_t)brow * 128 + col * 2);
            cp16(st + OBH + sw, Bh + base + i * 8);
            cp16(st + OBL + sw, Bl + base + i * 8);
        }
    };
    auto stXinline = [&](uint32_t st) {   // L1 / P only (BM=64, K=64 fp32)
        const int row = tid >> 2, cb = (tid & 3) * 16;
        const float* src = (TMODE == TM_L1) ? pX : g_y;
        const float* xr = src + (size_t)(m0 + row) * 64 + cb;
#pragma unroll
        for (int i = 0; i < 4; i++) {
            float4 v = *(const float4*)(xr + i * 4);
            uint32_t h01, l01, h23, l23;
            split2(v.x, v.y, h01, l01);
            split2(v.z, v.w, h23, l23);
            uint32_t sw = sw128((uint32_t)row * 128 + (cb + i * 4) * 2);
            sts_v2(st + OXH + sw, h01, h23);
            sts_v2(st + OXL + sw, l01, l23);
        }
    };

    float acc0[2][NT][4], acc1[2][NT][4], acc2[2][NT][4];
#pragma unroll
    for (int mt = 0; mt < 2; mt++)
#pragma unroll
        for (int nt = 0; nt < NT; nt++)
#pragma unroll
            for (int i = 0; i < 4; i++) {
                acc0[mt][nt][i] = 0.f;
                acc1[mt][nt][i] = 0.f;
                acc2[mt][nt][i] = 0.f;
            }

    if constexpr (PIPE) {
#pragma unroll
        for (int s = 0; s < NSTAGE - 1; s++) {
            const uint32_t st = sb + (uint32_t)s * STAGE;
            cpX(s, st); cpB(s, st); cp_commit();
        }
    } else {
        cpB(0, sb); cp_commit(); stXinline(sb);
    }

    for (int ch = 0; ch < NCHUNK; ch++) {
        const uint32_t st = sb + (uint32_t)(ch % NSTAGE) * STAGE;
        if constexpr (PIPE) {
            const int pf = ch + NSTAGE - 1;
            if (pf < NCHUNK) {
                const uint32_t st2 = sb + (uint32_t)(pf % NSTAGE) * STAGE;
                cpX(pf, st2); cpB(pf, st2);
            }
            cp_commit();
            cp_wait<NSTAGE - 1>();
        } else {
            cp_wait<0>();
        }
        __syncthreads();

#pragma unroll
        for (int ks = 0; ks < 4; ks++) {
            uint32_t aH[2][4], aL[2][4];
#pragma unroll
            for (int mt = 0; mt < 2; mt++) {
                uint32_t byte = (uint32_t)(wm + mt * 16 + (lane & 15)) * 128
                              + ks * 32 + (lane >> 4) * 16;
                uint32_t sw = sw128(byte);
                ldsm_x4(aH[mt], st + OXH + sw);
                ldsm_x4(aL[mt], st + OXL + sw);
            }
            uint32_t bH[NT][2], bL[NT][2];
#pragma unroll
            for (int nt = 0; nt < NT; nt++) {
                uint32_t byte = (uint32_t)(wn + nt * 8 + (lane & 7)) * 128
                              + ks * 32 + ((lane >> 3) & 1) * 16;
                uint32_t sw = sw128(byte);
                ldsm_x2(bH[nt], st + OBH + sw);
                ldsm_x2(bL[nt], st + OBL + sw);
            }
#pragma unroll
            for (int mt = 0; mt < 2; mt++)
#pragma unroll
                for (int nt = 0; nt < NT; nt++) {
                    mma16816(acc0[mt][nt], aH[mt], bH[nt]);
                    mma16816(acc1[mt][nt], aH[mt], bL[nt]);
                    mma16816(acc2[mt][nt], aL[mt], bH[nt]);
                }
        }
        __syncthreads();
    }

#pragma unroll
    for (int mt = 0; mt < 2; mt++)
#pragma unroll
        for (int nt = 0; nt < NT; nt++) {
            const int r0  = m0 + wm + mt * 16 + (lane >> 2);
            const int col = n0 + wn + nt * 8 + (lane & 3) * 2;
#pragma unroll
            for (int half = 0; half < 2; half++) {
                const int row = r0 + half * 8;
                const float e0 = acc0[mt][nt][half*2]   + acc1[mt][nt][half*2]
                               + acc2[mt][nt][half*2];
                const float e1 = acc0[mt][nt][half*2+1] + acc1[mt][nt][half*2+1]
                               + acc2[mt][nt][half*2+1];
                const size_t idx = (size_t)row * NH + col;
                if constexpr (TMODE == TM_L1) {
                    float tv = pT[row];
                    float h0 = tanhf(e0 + tv * w1row[col]     + pC[col]);
                    float h1 = tanhf(e1 + tv * w1row[col + 1] + pC[col + 1]);
                    *(float2*)(g_h1 + idx) = make_float2(h0, h1);
                    store_split(g_h1s_h, g_h1s_l, idx, h0, h1);
                    float a0 = 1.f - h0 * h0, a1v = 1.f - h1 * h1;
                    store_split(g_a1s_h, g_a1s_l, idx, a0, a1v);
                    store_split(g_d1s_h, g_d1s_l, idx,
                                a0 * w1row[col], a1v * w1row[col + 1]);
                } else if constexpr (TMODE == TM_H2) {
                    if (zm == 0) {
                        float h0 = tanhf(e0 + pC[col]);
                        float h1 = tanhf(e1 + pC[col + 1]);
                        *(float2*)(g_h2 + idx) = make_float2(h0, h1);
                        store_split(g_a2s_h, g_a2s_l, idx,
                                    1.f - h0 * h0, 1.f - h1 * h1);
                    } else if (zm == 1) {
                        *(float2*)(g_r2 + idx) = make_float2(e0, e1);
                    } else {
                        *(float2*)(g_V + idx) = make_float2(e0, e1);
                    }
                } else if constexpr (TMODE == TM_QWU) {
                    float* o = zm ? g_r1 : g_U;
                    *(float2*)(o + idx) = make_float2(e0, e1);
                } else {  // TM_P
                    float2 h = *(const float2*)(g_h2 + idx);
                    float2 v = *(const float2*)(g_V + idx);
                    float w0 = (1.f - h.x * h.x) * (e0 - 2.f * h.x * v.x);
                    float w1 = (1.f - h.y * h.y) * (e1 - 2.f * h.y * v.y);
                    store_split(g_wbs_h, g_wbs_l, idx, w0, w1);
                }
            }
        }
}

// ---------------- split-K tensor thin GEMMs (64 blocks) -----------------------
// grid (KSPLIT, NB/128): one 128x64x64 MMA chunk per block.
// S: X = h2 (inline split; fused s_t partials);  B = W3^T pre-split.
// LOSS: X = c = a1*(qw - 2 h1 U) (inline split); B = W1x pre-split.
template<int LOSS>
__global__ void __launch_bounds__(256, 1)
tsplit() {
    extern __shared__ __align__(1024) char tsm[];
    const uint32_t sb = smem_u32(tsm);
    constexpr uint32_t XSZ = 128 * 128;
    constexpr uint32_t OXH = 0, OXL = XSZ, OBH = 2 * XSZ, OBL = 2 * XSZ + 8192;
    const int tid = threadIdx.x, lane = tid & 31, wid = tid >> 5;
    const int kc = blockIdx.x * 64, m0 = blockIdx.y * 128;
    const int wm = (wid & 3) * 32, wn = (wid >> 2) * 32;

    // B tile via cp.async
    {
        const int brow = tid >> 2, bcb = (tid & 3) * 16;
        const bf16* Bh = LOSS ? g_W1xs_h : g_W3Ts_h;
        const bf16* Bl = LOSS ? g_W1xs_l : g_W3Ts_l;
        size_t base = (size_t)brow * NH + kc + bcb;
#pragma unroll
        for (int i = 0; i < 2; i++) {
            int col = bcb + i * 8;
            uint32_t sw = sw128((uint32_t)brow * 128 + col * 2);
            cp16(sb + OBH + sw, Bh + base + i * 8);
            cp16(sb + OBL + sw, Bl + base + i * 8);
        }
        cp_commit();
    }
    // X tile: inline fp32 -> hi/lo split
    float stp = 0.f;
    {
        const int row = tid >> 1, cb = (tid & 1) * 32;
        size_t base = (size_t)(m0 + row) * NH + kc + cb;
#pragma unroll
        for (int i = 0; i < 8; i++) {
            float4 v;
            if constexpr (!LOSS) {
                v = *(const float4*)(g_h2 + base + i * 4);
                float4 z = *(const float4*)(g_r2 + base + i * 4);
                float4 w = *(const float4*)(g_w3s + kc + cb + i * 4);
                stp += (1.f - v.x*v.x) * z.x * w.x + (1.f - v.y*v.y) * z.y * w.y
                     + (1.f - v.z*v.z) * z.z * w.z + (1.f - v.w*v.w) * z.w * w.w;
            } else {
                float4 q = *(const float4*)(g_r1 + base + i * 4);
                float4 h = *(const float4*)(g_h1 + base + i * 4);
                float4 u = *(const float4*)(g_U + base + i * 4);
                v.x = (1.f - h.x*h.x) * (q.x - 2.f * h.x * u.x);
                v.y = (1.f - h.y*h.y) * (q.y - 2.f * h.y * u.y);
                v.z = (1.f - h.z*h.z) * (q.z - 2.f * h.z * u.z);
                v.w = (1.f - h.w*h.w) * (q.w - 2.f * h.w * u.w);
            }
            uint32_t h01, l01, h23, l23;
            split2(v.x, v.y, h01, l01);
            split2(v.z, v.w, h23, l23);
            uint32_t sw = sw128((uint32_t)row * 128 + (cb + i * 4) * 2);
            sts_v2(sb + OXH + sw, h01, h23);
            sts_v2(sb + OXL + sw, l01, l23);
        }
    }
    cp_wait<0>();
    __syncthreads();

    float acc0[2][4][4], acc1[2][4][4], acc2[2][4][4];
#pragma unroll
    for (int mt = 0; mt < 2; mt++)
#pragma unroll
        for (int nt = 0; nt < 4; nt++)
#pragma unroll
            for (int i = 0; i < 4; i++) {
                acc0[mt][nt][i] = 0.f; acc1[mt][nt][i] = 0.f; acc2[mt][nt][i] = 0.f;
            }

#pragma unroll
    for (int ks = 0; ks < 4; ks++) {
        uint32_t aH[2][4], aL[2][4];
#pragma unroll
        for (int mt = 0; mt < 2; mt++) {
            uint32_t byte = (uint32_t)(wm + mt * 16 + (lane & 15)) * 128
                          + ks * 32 + (lane >> 4) * 16;
            uint32_t sw = sw128(byte);
            ldsm_x4(aH[mt], sb + OXH + sw);
            ldsm_x4(aL[mt], sb + OXL + sw);
        }
        uint32_t bH[4][2], bL[4][2];
#pragma unroll
        for (int nt = 0; nt < 4; nt++) {
            uint32_t byte = (uint32_t)(wn + nt * 8 + (lane & 7)) * 128
                          + ks * 32 + ((lane >> 3) & 1) * 16;
            uint32_t sw = sw128(byte);
            ldsm_x2(bH[nt], sb + OBH + sw);
            ldsm_x2(bL[nt], sb + OBL + sw);
        }
#pragma unroll
        for (int mt = 0; mt < 2; mt++)
#pragma unroll
            for (int nt = 0; nt < 4; nt++) {
                mma16816(acc0[mt][nt], aH[mt], bH[nt]);
                mma16816(acc1[mt][nt], aH[mt], bL[nt]);
                mma16816(acc2[mt][nt], aL[mt], bH[nt]);
            }
    }

    float* ob = (LOSS ? g_gp : g_sp) + (size_t)blockIdx.x * NB * ND;
#pragma unroll
    for (int mt = 0; mt < 2; mt++)
#pragma unroll
        for (int nt = 0; nt < 4; nt++) {
            const int r0  = m0 + wm + mt * 16 + (lane >> 2);
            const int col = wn + nt * 8 + (lane & 3) * 2;
#pragma unroll
            for (int half = 0; half < 2; half++) {
                const int row = r0 + half * 8;
                const float e0 = acc0[mt][nt][half*2]   + acc1[mt][nt][half*2]
                               + acc2[mt][nt][half*2];
                const float e1 = acc0[mt][nt][half*2+1] + acc1[mt][nt][half*2+1]
                               + acc2[mt][nt][half*2+1];
                *(float2*)(ob + (size_t)row * ND + col) = make_float2(e0, e1);
            }
        }

    if constexpr (!LOSS) {
        stp += __shfl_xor_sync(0xffffffffu, stp, 1, 2);
        if (!(tid & 1))
            g_stp[(size_t)(m0 + (tid >> 1)) * KSPLIT + blockIdx.x] = stp;
    }
}

// ---------------- reduce S: s = Σ sp + b3; y = 2s + x; s_t = Σ stp ------------
__global__ void __launch_bounds__(256)
reduce_s(const float* __restrict__ b3, const float* __restrict__ x) {
    const int tid = threadIdx.x;
    const size_t gi = (size_t)blockIdx.x * 256 + tid;
    const int col = (int)(gi & 63);
    float s = b3[col];
#pragma unroll
    for (int kp = 0; kp < KSPLIT; kp++) s += g_sp[(size_t)kp * NB * ND + gi];
    g_s[gi] = s;
    g_y[gi] = 2.f * s + x[gi];
    const size_t row0 = (size_t)blockIdx.x * 4;
    if (tid < 4) {
        float st = 0.f;
#pragma unroll
        for (int kp = 0; kp < KSPLIT; kp++)
            st += g_stp[(row0 + tid) * KSPLIT + kp];
        g_st[row0 + tid] = st;
    }
}

// ---------------- reduce LOSS: out = mean |st - 0.5 beta (Σ gp + s)| ----------
__global__ void __launch_bounds__(256)
reduce_loss(const float* __restrict__ beta, float* __restrict__ out) {
    __shared__ float red[8];
    const int tid = threadIdx.x;
    const int row = blockIdx.x * 4 + (tid >> 6);
    const int col = tid & 63;
    const size_t idx = (size_t)row * ND + col;
    float g = g_s[idx];
#pragma unroll
    for (int kp = 0; kp < KSPLIT; kp++) g += g_gp[(size_t)kp * NB * ND + idx];
    float v = fabsf(g_st[row] - 0.5f * beta[row] * g);
#pragma unroll
    for (int o = 16; o; o >>= 1) v += __shfl_xor_sync(0xffffffffu, v, o);
    if ((tid & 31) == 0) red[tid >> 5] = v;
    __syncthreads();
    if (tid < 4)
        out[blockIdx.x * 4 + tid] = (red[tid*2] + red[tid*2+1]) * (1.f / 64.f);
}

// ---------------- launch -----------------------------------------------------
#define SM_H2   (3 * (2 * 128 * 128 + 16384))   // 147456 (3-stage, BM=128)
#define SM_P64  (4 * (2 * 64 * 128 + 16384))    // 131072 (4-stage, BM=64)
#define SM_S64  (2 * 64 * 128 + 16384)          // 32768  (single-stage)
#define SM_TS   (2 * 128 * 128 + 16384)         // 49152  (tsplit)

extern "C" void kernel_launch(void* const* d_in, const int* in_sizes, int n_in,
                              void* d_out, int out_size) {
    const float* x    = (const float*)d_in[0];
    const float* t    = (const float*)d_in[1];
    const float* beta = (const float*)d_in[2];
    const float* W1   = (const float*)d_in[3];
    const float* b1   = (const float*)d_in[4];
    const float* W2   = (const float*)d_in[5];
    const float* b2   = (const float*)d_in[6];
    const float* W3   = (const float*)d_in[7];
    const float* b3   = (const float*)d_in[8];
    float* out = (float*)d_out;
    const float* w1t = W1 + (size_t)ND * NH;   // W1 t-row

    cudaFuncSetAttribute(tmma<TM_L1, 64>,  cudaFuncAttributeMaxDynamicSharedMemorySize, SM_S64);
    cudaFuncSetAttribute(tmma<TM_H2, 128>, cudaFuncAttributeMaxDynamicSharedMemorySize, SM_H2);
    cudaFuncSetAttribute(tmma<TM_QWU, 64>, cudaFuncAttributeMaxDynamicSharedMemorySize, SM_P64);
    cudaFuncSetAttribute(tmma<TM_P, 64>,   cudaFuncAttributeMaxDynamicSharedMemorySize, SM_S64);
    cudaFuncSetAttribute(tsplit<0>, cudaFuncAttributeMaxDynamicSharedMemorySize, SM_TS);
    cudaFuncSetAttribute(tsplit<1>, cudaFuncAttributeMaxDynamicSharedMemorySize, SM_TS);

    dim3 gTS  (KSPLIT, NB/128);    // (8,8) = 64 blocks
    dim3 gT2  (NH/64, NB/128, 3);  // 192 blocks: {h2raw, z2, V}
    dim3 gQWU (NH/64, NB/64,  2);  // 256 blocks: {U, qw}
    dim3 gT64 (NH/64, NB/64);      // 128 blocks

    prep_kernel<<<dim3(NH/16, NH/16), dim3(16,16)>>>(W1, W2, W3);
    // h1 = tanh([x,t]@W1 + b1); writes h1, h1s, a1s, d1s
    tmma<TM_L1, 64><<<gT64, 256, SM_S64>>>(x, b1, t, w1t);
    // z0: h2 = tanh(h1@W2 + b2) (+a2s); z1: z2 = d1@W2; z2: V = a1@A
    tmma<TM_H2, 128><<<gT2, 256, SM_H2>>>(nullptr, b2, nullptr, nullptr);
    // tensor split-K partials of s = h2@W3 (+ s_t partials) [4th -> ncu]
    tsplit<0><<<gTS, 256, SM_TS>>>();
    // s, y, s_t finalize
    reduce_s<<<NB*ND/256, 256>>>(b3, x);
    // P = y@W3^T; wb = a2*(P - 2 h2 V) -> wbs
    tmma<TM_P, 64><<<gT64, 256, SM_S64>>>(nullptr, nullptr, nullptr, nullptr);
    // z0: U = a2@A'; z1: qw = wb@W2^T
    tmma<TM_QWU, 64><<<gQWU, 256, SM_P64>>>(nullptr, nullptr, nullptr, nullptr);
    // tensor split-K partials of G = c@W1x^T (c inline)
    tsplit<1><<<gTS, 256, SM_TS>>>();
    // loss = mean |s_t - 0.5 beta (G + s)|
    reduce_loss<<<NB/4, 256>>>(beta, out);
}

// round 17
// speedup vs baseline: 1.2482x; 1.0409x over previous
#include <cuda_runtime.h>
#include <cuda_bf16.h>
#include <math.h>
#include <stdint.h>

#define NB 1024
#define ND 64
#define NH 512
#define KSPLIT 8

typedef __nv_bfloat16 bf16;

// ---------------- fp32 scratch ----------------
__device__ __align__(256) float g_W1T[NH*ND];   // [k,i] = W1[i,k]
__device__ __align__(256) float g_w3s[NH];
__device__ __align__(256) float g_h1 [NB*NH];
__device__ __align__(256) float g_h2 [NB*NH];
__device__ __align__(256) float g_U  [NB*NH];
__device__ __align__(256) float g_V  [NB*NH];
__device__ __align__(256) float g_r1 [NB*NH];   // qw
__device__ __align__(256) float g_r2 [NB*NH];   // z2
__device__ __align__(256) float g_s  [NB*ND];
__device__ __align__(256) float g_y  [NB*ND];
__device__ __align__(256) float g_st [NB];
__device__ __align__(256) float g_sp [KSPLIT*NB*ND];   // split-K partials (S)
__device__ __align__(256) float g_gp [KSPLIT*NB*ND];   // split-K partials (LOSS)
__device__ __align__(256) float g_stp[NB*KSPLIT];      // s_t partials

// ---------------- bf16 hi/lo pre-split scratch ----------------
__device__ __align__(256) bf16 g_W1Ts_h[NH*ND], g_W1Ts_l[NH*ND]; // [n,k]=W1[k,n]
__device__ __align__(256) bf16 g_W3s_h [NH*ND], g_W3s_l [NH*ND]; // [n,j]=W3[n,j]
__device__ __align__(256) bf16 g_W1xs_h[ND*NH], g_W1xs_l[ND*NH]; // [j,k]=W1[j,k] (x rows)
__device__ __align__(256) bf16 g_W3Ts_h[ND*NH], g_W3Ts_l[ND*NH]; // [n,k]=W3[k,n]
__device__ __align__(256) bf16 g_W2Ts_h[NH*NH], g_W2Ts_l[NH*NH]; // [n,k]=W2[k,n]
__device__ __align__(256) bf16 g_W2s_h [NH*NH], g_W2s_l [NH*NH]; // [n,k]=W2[n,k]
__device__ __align__(256) bf16 g_As_h  [NH*NH], g_As_l  [NH*NH]; // [n,k]=A[n,k]
__device__ __align__(256) bf16 g_ATs_h [NH*NH], g_ATs_l [NH*NH]; // [n,k]=A[k,n]
__device__ __align__(256) bf16 g_h1s_h [NB*NH], g_h1s_l [NB*NH];
__device__ __align__(256) bf16 g_d1s_h [NB*NH], g_d1s_l [NB*NH];
__device__ __align__(256) bf16 g_a1s_h [NB*NH], g_a1s_l [NB*NH];
__device__ __align__(256) bf16 g_a2s_h [NB*NH], g_a2s_l [NB*NH];
__device__ __align__(256) bf16 g_wbs_h [NB*NH], g_wbs_l [NB*NH];

// ---------------- helpers ------------------------------------------------
__device__ __forceinline__ uint32_t smem_u32(const void* p) {
    return (uint32_t)__cvta_generic_to_shared(p);
}
__device__ __forceinline__ void sts_v2(uint32_t addr, uint32_t a, uint32_t b) {
    asm volatile("st.shared.v2.b32 [%0], {%1,%2};" :: "r"(addr), "r"(a), "r"(b));
}
__device__ __forceinline__ void cp16(uint32_t saddr, const void* gaddr) {
    asm volatile("cp.async.cg.shared.global [%0], [%1], 16;"
                 :: "r"(saddr), "l"(gaddr));
}
__device__ __forceinline__ void cp_commit() {
    asm volatile("cp.async.commit_group;" ::: "memory");
}
template<int N> __device__ __forceinline__ void cp_wait() {
    asm volatile("cp.async.wait_group %0;" :: "n"(N) : "memory");
}
__device__ __forceinline__ void split2(float x0, float x1, uint32_t& hi, uint32_t& lo) {
    bf16 h0 = __float2bfloat16(x0), h1 = __float2bfloat16(x1);
    bf16 l0 = __float2bfloat16(x0 - __bfloat162float(h0));
    bf16 l1 = __float2bfloat16(x1 - __bfloat162float(h1));
    __nv_bfloat162 H; H.x = h0; H.y = h1;
    __nv_bfloat162 L; L.x = l0; L.y = l1;
    hi = *reinterpret_cast<uint32_t*>(&H);
    lo = *reinterpret_cast<uint32_t*>(&L);
}
__device__ __forceinline__ void splitf(float v, bf16* H, bf16* L, size_t idx) {
    bf16 h = __float2bfloat16(v);
    H[idx] = h;
    L[idx] = __float2bfloat16(v - __bfloat162float(h));
}
__device__ __forceinline__ void store_split(bf16* H, bf16* L, size_t idx,
                                            float v0, float v1) {
    uint32_t hi, lo; split2(v0, v1, hi, lo);
    *reinterpret_cast<uint32_t*>(H + idx) = hi;
    *reinterpret_cast<uint32_t*>(L + idx) = lo;
}
__device__ __forceinline__ void ldsm_x4(uint32_t* r, uint32_t addr) {
    asm volatile("ldmatrix.sync.aligned.m8n8.x4.shared.b16 {%0,%1,%2,%3}, [%4];"
                 : "=r"(r[0]), "=r"(r[1]), "=r"(r[2]), "=r"(r[3]) : "r"(addr));
}
__device__ __forceinline__ void ldsm_x2(uint32_t* r, uint32_t addr) {
    asm volatile("ldmatrix.sync.aligned.m8n8.x2.shared.b16 {%0,%1}, [%2];"
                 : "=r"(r[0]), "=r"(r[1]) : "r"(addr));
}
__device__ __forceinline__ void mma16816(float* c, const uint32_t* a, const uint32_t* b) {
    asm volatile(
        "mma.sync.aligned.m16n8k16.row.col.f32.bf16.bf16.f32 "
        "{%0,%1,%2,%3}, {%4,%5,%6,%7}, {%8,%9}, {%0,%1,%2,%3};"
        : "+f"(c[0]), "+f"(c[1]), "+f"(c[2]), "+f"(c[3])
        : "r"(a[0]), "r"(a[1]), "r"(a[2]), "r"(a[3]), "r"(b[0]), "r"(b[1]));
}
__device__ __forceinline__ uint32_t sw128(uint32_t byte) {
    return byte ^ ((byte >> 3) & 0x70);
}

// ---------------- prep: weights + derived matrices, pre-split ----------------
__global__ void prep_kernel(const float* __restrict__ W1,
                            const float* __restrict__ W2,
                            const float* __restrict__ W3) {
    __shared__ float w2ts[16][17];
    const int tx = threadIdx.x, ty = threadIdx.y;
    const int r = blockIdx.y * 16 + ty;
    const int c = blockIdx.x * 16 + tx;
    w2ts[ty][tx] = W2[(size_t)(blockIdx.x * 16 + ty) * NH + blockIdx.y * 16 + tx];
    __syncthreads();
    float w2rc = W2[(size_t)r * NH + c];
    float w2cr = w2ts[tx][ty];
    float d1 = 0.f, d2 = 0.f;
#pragma unroll
    for (int i = 0; i < ND; i++) {
        d1 += W3[c * ND + i] * W1[i * NH + r];
        d2 += W3[r * ND + i] * W1[i * NH + c];
    }
    const size_t idx = (size_t)r * NH + c;
    splitf(w2rc,      g_W2s_h,  g_W2s_l,  idx);
    splitf(w2cr,      g_W2Ts_h, g_W2Ts_l, idx);
    splitf(w2rc * d1, g_As_h,   g_As_l,   idx);   // A[r,c]
    splitf(w2cr * d2, g_ATs_h,  g_ATs_l,  idx);   // A[c,r]
    if (c < ND) {
        float w1v = W1[c * NH + r];
        g_W1T[r * ND + c] = w1v;
        splitf(w1v,          g_W1Ts_h, g_W1Ts_l, (size_t)r * ND + c);
        splitf(W3[r*ND + c], g_W3s_h,  g_W3s_l,  (size_t)r * ND + c);
    }
    if (blockIdx.x < 4) {
        const int j = blockIdx.x * 16 + ty;        // 0..63
        const int k = blockIdx.y * 16 + tx;        // 0..511
        splitf(W1[(size_t)j * NH + k], g_W1xs_h, g_W1xs_l, (size_t)j * NH + k);
        splitf(W3[(size_t)k * ND + j], g_W3Ts_h, g_W3Ts_l, (size_t)j * NH + k);
    }
    if (blockIdx.y == 0 && ty == 0) {
        float s1 = 0.f;
#pragma unroll
        for (int jj = 0; jj < ND; jj++) s1 += W3[c * ND + jj];
        g_w3s[c] = s1;
    }
}

// ---------------- tensor GEMMs -----------------------------------------------
enum { TM_L1 = 0, TM_H2 = 1, TM_QWU = 2, TM_P = 3 };

template<int TMODE, int BM>
__global__ void __launch_bounds__(256, 1)
tmma(const float* __restrict__ pX, const float* __restrict__ pC,
     const float* __restrict__ pT, const float* __restrict__ w1row) {
    extern __shared__ __align__(1024) char tsm[];
    const uint32_t sb = smem_u32(tsm);
    constexpr bool PIPE = (TMODE == TM_H2 || TMODE == TM_QWU);
    constexpr int NCHUNK = PIPE ? 8 : 1;
    constexpr int NSTAGE = PIPE ? ((BM == 128) ? 3 : 4) : 1;
    constexpr uint32_t XSZ = BM * 128;
    constexpr uint32_t OXH = 0, OXL = XSZ, OBH = 2 * XSZ, OBL = 2 * XSZ + 8192;
    constexpr uint32_t STAGE = 2 * XSZ + 16384;
    constexpr int NT = (BM == 128) ? 4 : 2;
    constexpr int LDBW = (TMODE == TM_L1 || TMODE == TM_P) ? ND : NH;

    const int tid = threadIdx.x, lane = tid & 31, wid = tid >> 5;
    const int zm = blockIdx.z;
    const int n0 = blockIdx.x * 64, m0 = blockIdx.y * BM;
    const int wm = (BM == 128 ? (wid & 3) : (wid & 1)) * 32;
    const int wn = (BM == 128 ? (wid >> 2) * 32 : (wid >> 1) * 16);

    const bf16 *Xh = nullptr, *Xl = nullptr;
    if constexpr (TMODE == TM_H2) {
        Xh = (zm == 0) ? g_h1s_h : (zm == 1) ? g_d1s_h : g_a1s_h;
        Xl = (zm == 0) ? g_h1s_l : (zm == 1) ? g_d1s_l : g_a1s_l;
    }
    else if constexpr (TMODE == TM_QWU) {
        Xh = zm ? g_wbs_h : g_a2s_h;
        Xl = zm ? g_wbs_l : g_a2s_l;
    }
    const bf16 *Bh, *Bl;
    if constexpr (TMODE == TM_L1)      { Bh = g_W1Ts_h; Bl = g_W1Ts_l; }
    else if constexpr (TMODE == TM_H2) {
        Bh = (zm <= 1) ? g_W2Ts_h : g_ATs_h;
        Bl = (zm <= 1) ? g_W2Ts_l : g_ATs_l;
    }
    else if constexpr (TMODE == TM_QWU) {
        Bh = zm ? g_W2s_h : g_As_h;
        Bl = zm ? g_W2s_l : g_As_l;
    }
    else { Bh = g_W3s_h; Bl = g_W3s_l; }

    const int xrow = (BM == 128) ? (tid >> 1) : (tid >> 2);
    const int xcb  = (BM == 128) ? ((tid & 1) * 32) : ((tid & 3) * 16);
    const int brow = tid >> 2, bcb = (tid & 3) * 16;

    auto cpX = [&](int ch, uint32_t st) {
        constexpr int NI = (BM == 128) ? 4 : 2;
        size_t base = (size_t)(m0 + xrow) * NH + ch * 64 + xcb;
#pragma unroll
        for (int i = 0; i < NI; i++) {
            int col = xcb + i * 8;
            uint32_t sw = sw128((uint32_t)xrow * 128 + col * 2);
            cp16(st + OXH + sw, Xh + base + i * 8);
            cp16(st + OXL + sw, Xl + base + i * 8);
        }
    };
    auto cpB = [&](int ch, uint32_t st) {
        size_t base = (size_t)(n0 + brow) * LDBW + (PIPE ? ch * 64 : 0) + bcb;
#pragma unroll
        for (int i = 0; i < 2; i++) {
            int col = bcb + i * 8;
            uint32_t sw = sw128((uint32_t)brow * 128 + col * 2);
            cp16(st + OBH + sw, Bh + base + i * 8);
            cp16(st + OBL + sw, Bl + base + i * 8);
        }
    };
    auto stXinline = [&](uint32_t st) {   // L1 / P only (BM=64, K=64 fp32)
        const int row = tid >> 2, cb = (tid & 3) * 16;
        const float* src = (TMODE == TM_L1) ? pX : g_y;
        const float* xr = src + (size_t)(m0 + row) * 64 + cb;
#pragma unroll
        for (int i = 0; i < 4; i++) {
            float4 v = *(const float4*)(xr + i * 4);
            uint32_t h01, l01, h23, l23;
            split2(v.x, v.y, h01, l01);
            split2(v.z, v.w, h23, l23);
            uint32_t sw = sw128((uint32_t)row * 128 + (cb + i * 4) * 2);
            sts_v2(st + OXH + sw, h01, h23);
            sts_v2(st + OXL + sw, l01, l23);
        }
    };

    float acc0[2][NT][4], acc1[2][NT][4], acc2[2][NT][4];
#pragma unroll
    for (int mt = 0; mt < 2; mt++)
#pragma unroll
        for (int nt = 0; nt < NT; nt++)
#pragma unroll
            for (int i = 0; i < 4; i++) {
                acc0[mt][nt][i] = 0.f;
                acc1[mt][nt][i] = 0.f;
                acc2[mt][nt][i] = 0.f;
            }

    if constexpr (PIPE) {
#pragma unroll
        for (int s = 0; s < NSTAGE - 1; s++) {
            const uint32_t st = sb + (uint32_t)s * STAGE;
            cpX(s, st); cpB(s, st); cp_commit();
        }
    } else {
        cpB(0, sb); cp_commit(); stXinline(sb);
    }

    for (int ch = 0; ch < NCHUNK; ch++) {
        const uint32_t st = sb + (uint32_t)(ch % NSTAGE) * STAGE;
        if constexpr (PIPE) {
            const int pf = ch + NSTAGE - 1;
            if (pf < NCHUNK) {
                const uint32_t st2 = sb + (uint32_t)(pf % NSTAGE) * STAGE;
                cpX(pf, st2); cpB(pf, st2);
            }
            cp_commit();
            cp_wait<NSTAGE - 1>();
        } else {
            cp_wait<0>();
        }
        __syncthreads();

#pragma unroll
        for (int ks = 0; ks < 4; ks++) {
            uint32_t aH[2][4], aL[2][4];
#pragma unroll
            for (int mt = 0; mt < 2; mt++) {
                uint32_t byte = (uint32_t)(wm + mt * 16 + (lane & 15)) * 128
                              + ks * 32 + (lane >> 4) * 16;
                uint32_t sw = sw128(byte);
                ldsm_x4(aH[mt], st + OXH + sw);
                ldsm_x4(aL[mt], st + OXL + sw);
            }
            uint32_t bH[NT][2], bL[NT][2];
#pragma unroll
            for (int nt = 0; nt < NT; nt++) {
                uint32_t byte = (uint32_t)(wn + nt * 8 + (lane & 7)) * 128
                              + ks * 32 + ((lane >> 3) & 1) * 16;
                uint32_t sw = sw128(byte);
                ldsm_x2(bH[nt], st + OBH + sw);
                ldsm_x2(bL[nt], st + OBL + sw);
            }
#pragma unroll
            for (int mt = 0; mt < 2; mt++)
#pragma unroll
                for (int nt = 0; nt < NT; nt++) {
                    mma16816(acc0[mt][nt], aH[mt], bH[nt]);
                    mma16816(acc1[mt][nt], aH[mt], bL[nt]);
                    mma16816(acc2[mt][nt], aL[mt], bH[nt]);
                }
        }
        __syncthreads();
    }

#pragma unroll
    for (int mt = 0; mt < 2; mt++)
#pragma unroll
        for (int nt = 0; nt < NT; nt++) {
            const int r0  = m0 + wm + mt * 16 + (lane >> 2);
            const int col = n0 + wn + nt * 8 + (lane & 3) * 2;
#pragma unroll
            for (int half = 0; half < 2; half++) {
                const int row = r0 + half * 8;
                const float e0 = acc0[mt][nt][half*2]   + acc1[mt][nt][half*2]
                               + acc2[mt][nt][half*2];
                const float e1 = acc0[mt][nt][half*2+1] + acc1[mt][nt][half*2+1]
                               + acc2[mt][nt][half*2+1];
                const size_t idx = (size_t)row * NH + col;
                if constexpr (TMODE == TM_L1) {
                    float tv = pT[row];
                    float h0 = tanhf(e0 + tv * w1row[col]     + pC[col]);
                    float h1 = tanhf(e1 + tv * w1row[col + 1] + pC[col + 1]);
                    *(float2*)(g_h1 + idx) = make_float2(h0, h1);
                    store_split(g_h1s_h, g_h1s_l, idx, h0, h1);
                    float a0 = 1.f - h0 * h0, a1v = 1.f - h1 * h1;
                    store_split(g_a1s_h, g_a1s_l, idx, a0, a1v);
                    store_split(g_d1s_h, g_d1s_l, idx,
                                a0 * w1row[col], a1v * w1row[col + 1]);
                } else if constexpr (TMODE == TM_H2) {
                    if (zm == 0) {
                        float h0 = tanhf(e0 + pC[col]);
                        float h1 = tanhf(e1 + pC[col + 1]);
                        *(float2*)(g_h2 + idx) = make_float2(h0, h1);
                        store_split(g_a2s_h, g_a2s_l, idx,
                                    1.f - h0 * h0, 1.f - h1 * h1);
                    } else if (zm == 1) {
                        *(float2*)(g_r2 + idx) = make_float2(e0, e1);
                    } else {
                        *(float2*)(g_V + idx) = make_float2(e0, e1);
                    }
                } else if constexpr (TMODE == TM_QWU) {
                    float* o = zm ? g_r1 : g_U;
                    *(float2*)(o + idx) = make_float2(e0, e1);
                } else {  // TM_P
                    float2 h = *(const float2*)(g_h2 + idx);
                    float2 v = *(const float2*)(g_V + idx);
                    float w0 = (1.f - h.x * h.x) * (e0 - 2.f * h.x * v.x);
                    float w1 = (1.f - h.y * h.y) * (e1 - 2.f * h.y * v.y);
                    store_split(g_wbs_h, g_wbs_l, idx, w0, w1);
                }
            }
        }
}

// ---------------- split-K tensor thin GEMMs (128 blocks, BM=64) ---------------
// grid (KSPLIT, NB/64): one 64x64x64 MMA chunk per block.
// S: X = h2 (inline split; fused s_t partials);  B = W3^T pre-split.
// LOSS: X = c = a1*(qw - 2 h1 U) (inline split); B = W1x pre-split.
template<int LOSS>
__global__ void __launch_bounds__(256, 1)
tsplit() {
    extern __shared__ __align__(1024) char tsm[];
    const uint32_t sb = smem_u32(tsm);
    constexpr uint32_t XSZ = 64 * 128;
    constexpr uint32_t OXH = 0, OXL = XSZ, OBH = 2 * XSZ, OBL = 2 * XSZ + 8192;
    const int tid = threadIdx.x, lane = tid & 31, wid = tid >> 5;
    const int kc = blockIdx.x * 64, m0 = blockIdx.y * 64;
    const int wm = (wid & 1) * 32, wn = (wid >> 1) * 16;

    // B tile via cp.async
    {
        const int brow = tid >> 2, bcb = (tid & 3) * 16;
        const bf16* Bh = LOSS ? g_W1xs_h : g_W3Ts_h;
        const bf16* Bl = LOSS ? g_W1xs_l : g_W3Ts_l;
        size_t base = (size_t)brow * NH + kc + bcb;
#pragma unroll
        for (int i = 0; i < 2; i++) {
            int col = bcb + i * 8;
            uint32_t sw = sw128((uint32_t)brow * 128 + col * 2);
            cp16(sb + OBH + sw, Bh + base + i * 8);
            cp16(sb + OBL + sw, Bl + base + i * 8);
        }
        cp_commit();
    }
    // X tile: inline fp32 -> hi/lo split (64 rows, 4 float4/thread)
    float stp = 0.f;
    {
        const int row = tid >> 2, cb = (tid & 3) * 16;
        size_t base = (size_t)(m0 + row) * NH + kc + cb;
#pragma unroll
        for (int i = 0; i < 4; i++) {
            float4 v;
            if constexpr (!LOSS) {
                v = *(const float4*)(g_h2 + base + i * 4);
                float4 z = *(const float4*)(g_r2 + base + i * 4);
                float4 w = *(const float4*)(g_w3s + kc + cb + i * 4);
                stp += (1.f - v.x*v.x) * z.x * w.x + (1.f - v.y*v.y) * z.y * w.y
                     + (1.f - v.z*v.z) * z.z * w.z + (1.f - v.w*v.w) * z.w * w.w;
            } else {
                float4 q = *(const float4*)(g_r1 + base + i * 4);
                float4 h = *(const float4*)(g_h1 + base + i * 4);
                float4 u = *(const float4*)(g_U + base + i * 4);
                v.x = (1.f - h.x*h.x) * (q.x - 2.f * h.x * u.x);
                v.y = (1.f - h.y*h.y) * (q.y - 2.f * h.y * u.y);
                v.z = (1.f - h.z*h.z) * (q.z - 2.f * h.z * u.z);
                v.w = (1.f - h.w*h.w) * (q.w - 2.f * h.w * u.w);
            }
            uint32_t h01, l01, h23, l23;
            split2(v.x, v.y, h01, l01);
            split2(v.z, v.w, h23, l23);
            uint32_t sw = sw128((uint32_t)row * 128 + (cb + i * 4) * 2);
            sts_v2(sb + OXH + sw, h01, h23);
            sts_v2(sb + OXL + sw, l01, l23);
        }
    }
    cp_wait<0>();
    __syncthreads();

    float acc0[2][2][4], acc1[2][2][4], acc2[2][2][4];
#pragma unroll
    for (int mt = 0; mt < 2; mt++)
#pragma unroll
        for (int nt = 0; nt < 2; nt++)
#pragma unroll
            for (int i = 0; i < 4; i++) {
                acc0[mt][nt][i] = 0.f; acc1[mt][nt][i] = 0.f; acc2[mt][nt][i] = 0.f;
            }

#pragma unroll
    for (int ks = 0; ks < 4; ks++) {
        uint32_t aH[2][4], aL[2][4];
#pragma unroll
        for (int mt = 0; mt < 2; mt++) {
            uint32_t byte = (uint32_t)(wm + mt * 16 + (lane & 15)) * 128
                          + ks * 32 + (lane >> 4) * 16;
            uint32_t sw = sw128(byte);
            ldsm_x4(aH[mt], sb + OXH + sw);
            ldsm_x4(aL[mt], sb + OXL + sw);
        }
        uint32_t bH[2][2], bL[2][2];
#pragma unroll
        for (int nt = 0; nt < 2; nt++) {
            uint32_t byte = (uint32_t)(wn + nt * 8 + (lane & 7)) * 128
                          + ks * 32 + ((lane >> 3) & 1) * 16;
            uint32_t sw = sw128(byte);
            ldsm_x2(bH[nt], sb + OBH + sw);
            ldsm_x2(bL[nt], sb + OBL + sw);
        }
#pragma unroll
        for (int mt = 0; mt < 2; mt++)
#pragma unroll
            for (int nt = 0; nt < 2; nt++) {
                mma16816(acc0[mt][nt], aH[mt], bH[nt]);
                mma16816(acc1[mt][nt], aH[mt], bL[nt]);
                mma16816(acc2[mt][nt], aL[mt], bH[nt]);
            }
    }

    float* ob = (LOSS ? g_gp : g_sp) + (size_t)blockIdx.x * NB * ND;
#pragma unroll
    for (int mt = 0; mt < 2; mt++)
#pragma unroll
        for (int nt = 0; nt < 2; nt++) {
            const int r0  = m0 + wm + mt * 16 + (lane >> 2);
            const int col = wn + nt * 8 + (lane & 3) * 2;
#pragma unroll
            for (int half = 0; half < 2; half++) {
                const int row = r0 + half * 8;
                const float e0 = acc0[mt][nt][half*2]   + acc1[mt][nt][half*2]
                               + acc2[mt][nt][half*2];
                const float e1 = acc0[mt][nt][half*2+1] + acc1[mt][nt][half*2+1]
                               + acc2[mt][nt][half*2+1];
                *(float2*)(ob + (size_t)row * ND + col) = make_float2(e0, e1);
            }
        }

    if constexpr (!LOSS) {
        // 4 loader threads per row -> width-4 reduce
#pragma unroll
        for (int off = 2; off; off >>= 1)
            stp += __shfl_xor_sync(0xffffffffu, stp, off, 4);
        if (!(tid & 3))
            g_stp[(size_t)(m0 + (tid >> 2)) * KSPLIT + blockIdx.x] = stp;
    }
}

// ---------------- reduce S: s = Σ sp + b3; y = 2s + x; s_t = Σ stp ------------
__global__ void __launch_bounds__(256)
reduce_s(const float* __restrict__ b3, const float* __restrict__ x) {
    const int tid = threadIdx.x;
    const size_t gi = (size_t)blockIdx.x * 256 + tid;
    const int col = (int)(gi & 63);
    float s = b3[col];
#pragma unroll
    for (int kp = 0; kp < KSPLIT; kp++) s += g_sp[(size_t)kp * NB * ND + gi];
    g_s[gi] = s;
    g_y[gi] = 2.f * s + x[gi];
    const size_t row0 = (size_t)blockIdx.x * 4;
    if (tid < 4) {
        float st = 0.f;
#pragma unroll
        for (int kp = 0; kp < KSPLIT; kp++)
            st += g_stp[(row0 + tid) * KSPLIT + kp];
        g_st[row0 + tid] = st;
    }
}

// ---------------- reduce LOSS: out = mean |st - 0.5 beta (Σ gp + s)| ----------
__global__ void __launch_bounds__(256)
reduce_loss(const float* __restrict__ beta, float* __restrict__ out) {
    __shared__ float red[8];
    const int tid = threadIdx.x;
    const int row = blockIdx.x * 4 + (tid >> 6);
    const int col = tid & 63;
    const size_t idx = (size_t)row * ND + col;
    float g = g_s[idx];
#pragma unroll
    for (int kp = 0; kp < KSPLIT; kp++) g += g_gp[(size_t)kp * NB * ND + idx];
    float v = fabsf(g_st[row] - 0.5f * beta[row] * g);
#pragma unroll
    for (int o = 16; o; o >>= 1) v += __shfl_xor_sync(0xffffffffu, v, o);
    if ((tid & 31) == 0) red[tid >> 5] = v;
    __syncthreads();
    if (tid < 4)
        out[blockIdx.x * 4 + tid] = (red[tid*2] + red[tid*2+1]) * (1.f / 64.f);
}

// ---------------- launch -----------------------------------------------------
#define SM_H2   (3 * (2 * 128 * 128 + 16384))   // 147456 (3-stage, BM=128)
#define SM_P64  (4 * (2 * 64 * 128 + 16384))    // 131072 (4-stage, BM=64)
#define SM_S64  (2 * 64 * 128 + 16384)          // 32768  (single-stage)
#define SM_TS   (2 * 64 * 128 + 16384)          // 32768  (tsplit, BM=64)

extern "C" void kernel_launch(void* const* d_in, const int* in_sizes, int n_in,
                              void* d_out, int out_size) {
    const float* x    = (const float*)d_in[0];
    const float* t    = (const float*)d_in[1];
    const float* beta = (const float*)d_in[2];
    const float* W1   = (const float*)d_in[3];
    const float* b1   = (const float*)d_in[4];
    const float* W2   = (const float*)d_in[5];
    const float* b2   = (const float*)d_in[6];
    const float* W3   = (const float*)d_in[7];
    const float* b3   = (const float*)d_in[8];
    float* out = (float*)d_out;
    const float* w1t = W1 + (size_t)ND * NH;   // W1 t-row

    cudaFuncSetAttribute(tmma<TM_L1, 64>,  cudaFuncAttributeMaxDynamicSharedMemorySize, SM_S64);
    cudaFuncSetAttribute(tmma<TM_H2, 128>, cudaFuncAttributeMaxDynamicSharedMemorySize, SM_H2);
    cudaFuncSetAttribute(tmma<TM_QWU, 64>, cudaFuncAttributeMaxDynamicSharedMemorySize, SM_P64);
    cudaFuncSetAttribute(tmma<TM_P, 64>,   cudaFuncAttributeMaxDynamicSharedMemorySize, SM_S64);
    cudaFuncSetAttribute(tsplit<0>, cudaFuncAttributeMaxDynamicSharedMemorySize, SM_TS);
    cudaFuncSetAttribute(tsplit<1>, cudaFuncAttributeMaxDynamicSharedMemorySize, SM_TS);

    dim3 gTS  (KSPLIT, NB/64);     // (8,16) = 128 blocks
    dim3 gT2  (NH/64, NB/128, 3);  // 192 blocks: {h2raw, z2, V}
    dim3 gQWU (NH/64, NB/64,  2);  // 256 blocks: {U, qw}
    dim3 gT64 (NH/64, NB/64);      // 128 blocks

    prep_kernel<<<dim3(NH/16, NH/16), dim3(16,16)>>>(W1, W2, W3);
    // h1 = tanh([x,t]@W1 + b1); writes h1, h1s, a1s, d1s
    tmma<TM_L1, 64><<<gT64, 256, SM_S64>>>(x, b1, t, w1t);
    // z0: h2 = tanh(h1@W2 + b2) (+a2s); z1: z2 = d1@W2; z2: V = a1@A
    tmma<TM_H2, 128><<<gT2, 256, SM_H2>>>(nullptr, b2, nullptr, nullptr);
    // tensor split-K partials of s = h2@W3 (+ s_t partials) [4th -> ncu]
    tsplit<0><<<gTS, 256, SM_TS>>>();
    // s, y, s_t finalize
    reduce_s<<<NB*ND/256, 256>>>(b3, x);
    // P = y@W3^T; wb = a2*(P - 2 h2 V) -> wbs
    tmma<TM_P, 64><<<gT64, 256, SM_S64>>>(nullptr, nullptr, nullptr, nullptr);
    // z0: U = a2@A'; z1: qw = wb@W2^T
    tmma<TM_QWU, 64><<<gQWU, 256, SM_P64>>>(nullptr, nullptr, nullptr, nullptr);
    // tensor split-K partials of G = c@W1x^T (c inline)
    tsplit<1><<<gTS, 256, SM_TS>>>();
    // loss = mean |s_t - 0.5 beta (G + s)|
    reduce_loss<<<NB/4, 256>>>(beta, out);
}